// round 1
// baseline (speedup 1.0000x reference)
#include <cuda_runtime.h>
#include <math.h>
#include <stdint.h>

#define NN 50000
#define NE 1600000
#define DD 256
#define HH 8
#define HDIM 32
#define EDIM 32
#define D4 (4*DD)

// ---------------- scratch (device globals; no runtime allocation) ----------
__device__ float    g_xn[(size_t)NN*DD];
__device__ float    g_q [(size_t)NN*DD];
__device__ float    g_k [(size_t)NN*DD];
__device__ float    g_v [(size_t)NN*DD];
__device__ float    g_ep[(size_t)NE*HDIM];
__device__ float    g_scores[(size_t)NE*HH];
__device__ unsigned g_smax[(size_t)NN*HH];
__device__ float    g_ssum[(size_t)NN*HH];
__device__ float    g_agg[(size_t)NN*DD];
__device__ float    g_x1 [(size_t)NN*DD];
__device__ float    g_h  [(size_t)NN*D4];

// order-preserving float->uint encode for atomicMax
__device__ __forceinline__ unsigned fenc(float f) {
    unsigned u = __float_as_uint(f);
    return (u & 0x80000000u) ? ~u : (u | 0x80000000u);
}
__device__ __forceinline__ float fdec(unsigned u) {
    return (u & 0x80000000u) ? __uint_as_float(u & 0x7fffffffu)
                             : __uint_as_float(~u);
}

// ---------------- zero init (agg, ssum, smax) ------------------------------
__global__ void zero_kernel() {
    int i = blockIdx.x * blockDim.x + threadIdx.x;
    if (i < NN*DD) g_agg[i] = 0.f;
    if (i < NN*HH) { g_ssum[i] = 0.f; g_smax[i] = 0u; }
}

// ---------------- layernorm: one block (256 thr) per row -------------------
__global__ void ln_kernel(const float* __restrict__ in,
                          const float* __restrict__ g,
                          const float* __restrict__ b,
                          float* __restrict__ out) {
    int row = blockIdx.x;
    int t = threadIdx.x;
    float v = in[(size_t)row*DD + t];
    float s = v, s2 = v*v;
    #pragma unroll
    for (int off = 16; off; off >>= 1) {
        s  += __shfl_xor_sync(0xffffffffu, s,  off);
        s2 += __shfl_xor_sync(0xffffffffu, s2, off);
    }
    __shared__ float ws[8], ws2[8], mustd[2];
    int w = t >> 5, lane = t & 31;
    if (lane == 0) { ws[w] = s; ws2[w] = s2; }
    __syncthreads();
    if (t == 0) {
        float ts = 0.f, ts2 = 0.f;
        #pragma unroll
        for (int i = 0; i < 8; i++) { ts += ws[i]; ts2 += ws2[i]; }
        float mu = ts * (1.0f/DD);
        float var = ts2 * (1.0f/DD) - mu*mu;
        mustd[0] = mu;
        mustd[1] = 1.0f / sqrtf(var + 1e-5f);
    }
    __syncthreads();
    out[(size_t)row*DD + t] = (v - mustd[0]) * mustd[1] * g[t] + b[t];
}

// ---------------- fp32 SGEMM: C[M,N] = act(A[M,K] @ B[N,K]^T + bias) -------
// MODE 0: plain; MODE 1: C = res + scale*val; MODE 2: exact GELU
#define BM 128
#define BN 128
#define BK 8
#define TM 8
#define TN 8

__device__ __forceinline__ float gelu_exact(float x) {
    return 0.5f * x * (1.0f + erff(x * 0.70710678118654752f));
}

template<int MODE>
__global__ __launch_bounds__(256)
void sgemm_kernel(const float* __restrict__ A, const float* __restrict__ B,
                  const float* __restrict__ bias, float* __restrict__ C,
                  int M, int N, int K,
                  const float* __restrict__ res, const float* __restrict__ scalep) {
    __shared__ float As[BK][BM+4];
    __shared__ float Bs[BK][BN+4];
    int tid = threadIdx.x;
    int bm = blockIdx.y * BM;
    int bn = blockIdx.x * BN;
    int tx = tid & 15;
    int ty = tid >> 4;
    int lr = tid >> 1;           // 0..127
    int lc = (tid & 1) * 4;      // 0 or 4

    float acc[TM][TN];
    #pragma unroll
    for (int i = 0; i < TM; i++)
        #pragma unroll
        for (int j = 0; j < TN; j++) acc[i][j] = 0.f;

    bool avalid = (bm + lr) < M;
    const float* Aptr = A + (size_t)(bm + lr) * K + lc;
    const float* Bptr = B + (size_t)(bn + lr) * K + lc;

    float4 av = avalid ? *(const float4*)(Aptr) : make_float4(0,0,0,0);
    float4 bv = *(const float4*)(Bptr);

    for (int k0 = 0; k0 < K; k0 += BK) {
        As[lc+0][lr] = av.x; As[lc+1][lr] = av.y; As[lc+2][lr] = av.z; As[lc+3][lr] = av.w;
        Bs[lc+0][lr] = bv.x; Bs[lc+1][lr] = bv.y; Bs[lc+2][lr] = bv.z; Bs[lc+3][lr] = bv.w;
        __syncthreads();
        if (k0 + BK < K) {
            av = avalid ? *(const float4*)(Aptr + k0 + BK) : make_float4(0,0,0,0);
            bv = *(const float4*)(Bptr + k0 + BK);
        }
        #pragma unroll
        for (int kk = 0; kk < BK; kk++) {
            float a[TM], b[TN];
            *(float4*)&a[0] = *(const float4*)&As[kk][ty*TM];
            *(float4*)&a[4] = *(const float4*)&As[kk][ty*TM+4];
            *(float4*)&b[0] = *(const float4*)&Bs[kk][tx*TN];
            *(float4*)&b[4] = *(const float4*)&Bs[kk][tx*TN+4];
            #pragma unroll
            for (int i = 0; i < TM; i++)
                #pragma unroll
                for (int j = 0; j < TN; j++)
                    acc[i][j] = fmaf(a[i], b[j], acc[i][j]);
        }
        __syncthreads();
    }

    float scale = (MODE == 1) ? scalep[0] : 1.0f;
    #pragma unroll
    for (int i = 0; i < TM; i++) {
        int m = bm + ty*TM + i;
        if (m >= M) continue;
        #pragma unroll
        for (int j = 0; j < TN; j += 4) {
            int n = bn + tx*TN + j;
            float4 bi = *(const float4*)(bias + n);
            float4 v;
            v.x = acc[i][j+0] + bi.x;
            v.y = acc[i][j+1] + bi.y;
            v.z = acc[i][j+2] + bi.z;
            v.w = acc[i][j+3] + bi.w;
            if (MODE == 2) {
                v.x = gelu_exact(v.x); v.y = gelu_exact(v.y);
                v.z = gelu_exact(v.z); v.w = gelu_exact(v.w);
            }
            if (MODE == 1) {
                float4 r = *(const float4*)(res + (size_t)m*N + n);
                v.x = r.x + scale*v.x; v.y = r.y + scale*v.y;
                v.z = r.z + scale*v.z; v.w = r.w + scale*v.w;
            }
            *(float4*)(C + (size_t)m*N + n) = v;
        }
    }
}

// ---------------- edge projection: ep[E,32] = ef[E,32] @ We[32,32]^T + be --
__global__ __launch_bounds__(256)
void ep_kernel(const float* __restrict__ ef, const float* __restrict__ We,
               const float* __restrict__ be) {
    __shared__ float WeT[EDIM][HDIM+1];
    __shared__ float bsh[HDIM];
    int tid = threadIdx.x;
    for (int i = tid; i < HDIM*EDIM; i += 256) {
        int r = i / EDIM, c = i % EDIM;   // We[r][c], r=out dim, c=in dim
        WeT[c][r] = We[i];
    }
    if (tid < HDIM) bsh[tid] = be[tid];
    __syncthreads();
    int warp = tid >> 5, lane = tid & 31;
    size_t e = (size_t)blockIdx.x * 8 + warp;
    if (e >= NE) return;
    float f = ef[e*EDIM + lane];
    float acc = bsh[lane];
    #pragma unroll
    for (int k2 = 0; k2 < EDIM; k2++) {
        float fk = __shfl_sync(0xffffffffu, f, k2);
        acc = fmaf(fk, WeT[k2][lane], acc);
    }
    g_ep[e*HDIM + lane] = acc;
}

// ---------------- per-edge scores + segment max ----------------------------
__global__ __launch_bounds__(256)
void scores_kernel(const int* __restrict__ ei, const float* __restrict__ ew) {
    int lane = threadIdx.x & 31;
    size_t e = (size_t)blockIdx.x * 8 + (threadIdx.x >> 5);
    if (e >= NE) return;
    int src = ei[e];
    int dst = ei[NE + e];
    float epv = g_ep[e*HDIM + lane];
    const float* qr = g_q + (size_t)dst*DD + lane;
    const float* kr = g_k + (size_t)src*DD + lane;
    float acc[HH];
    #pragma unroll
    for (int h = 0; h < HH; h++)
        acc[h] = qr[h*HDIM] * (kr[h*HDIM] + epv);
    #pragma unroll
    for (int off = 16; off; off >>= 1)
        #pragma unroll
        for (int h = 0; h < HH; h++)
            acc[h] += __shfl_xor_sync(0xffffffffu, acc[h], off);
    if (lane == 0) {
        float w = ew[e] * 0.17677669529663687f;   // * HD^-0.5
        #pragma unroll
        for (int h = 0; h < HH; h++) {
            float s = acc[h] * w;
            g_scores[e*HH + h] = s;
            atomicMax(&g_smax[dst*HH + h], fenc(s));
        }
    }
}

// ---------------- exp(score - max) + segment sum (in place) ----------------
__global__ void expsum_kernel(const int* __restrict__ ei) {
    int i = blockIdx.x * blockDim.x + threadIdx.x;
    if (i >= NE*HH) return;
    int e = i >> 3;
    int h = i & 7;
    int dst = ei[NE + e];
    float m = fdec(g_smax[dst*HH + h]);
    float v = expf(g_scores[i] - m);
    g_scores[i] = v;
    atomicAdd(&g_ssum[dst*HH + h], v);
}

// ---------------- normalize + weighted scatter aggregate -------------------
__global__ __launch_bounds__(256)
void agg_kernel(const int* __restrict__ ei, float* __restrict__ attn_out) {
    int lane = threadIdx.x & 31;
    size_t e = (size_t)blockIdx.x * 8 + (threadIdx.x >> 5);
    if (e >= NE) return;
    int src = ei[e];
    int dst = ei[NE + e];
    float w = 0.f;
    if (lane < HH) {
        w = g_scores[e*HH + lane] / g_ssum[dst*HH + lane];
        if (attn_out) attn_out[e*HH + lane] = w;
    }
    float wh[HH];
    #pragma unroll
    for (int h = 0; h < HH; h++)
        wh[h] = __shfl_sync(0xffffffffu, w, h);
    const float* vr = g_v + (size_t)src*DD + lane;
    float* ar = g_agg + (size_t)dst*DD + lane;
    #pragma unroll
    for (int h = 0; h < HH; h++)
        atomicAdd(ar + h*HDIM, wh[h] * vr[h*HDIM]);
}

// ---------------------------------------------------------------------------
extern "C" void kernel_launch(void* const* d_in, const int* in_sizes, int n_in,
                              void* d_out, int out_size) {
    const float* x     = (const float*)d_in[0];
    const int*   ei    = (const int*)  d_in[1];
    const float* ef    = (const float*)d_in[2];
    const float* ew    = (const float*)d_in[3];
    const float* Wq    = (const float*)d_in[4];
    const float* bq    = (const float*)d_in[5];
    const float* Wk    = (const float*)d_in[6];
    const float* bk    = (const float*)d_in[7];
    const float* Wv    = (const float*)d_in[8];
    const float* bv    = (const float*)d_in[9];
    const float* We    = (const float*)d_in[10];
    const float* be    = (const float*)d_in[11];
    const float* Wo    = (const float*)d_in[12];
    const float* bo    = (const float*)d_in[13];
    const float* W1    = (const float*)d_in[14];
    const float* b1    = (const float*)d_in[15];
    const float* W2    = (const float*)d_in[16];
    const float* b2    = (const float*)d_in[17];
    const float* g1    = (const float*)d_in[18];
    const float* be1   = (const float*)d_in[19];
    const float* g2    = (const float*)d_in[20];
    const float* be2   = (const float*)d_in[21];
    const float* alpha = (const float*)d_in[22];
    const float* beta  = (const float*)d_in[23];

    float* out = (float*)d_out;
    float* out_x = out;
    float* out_attn = nullptr;
    if (out_size >= NN*DD + NE*HH) out_attn = out + (size_t)NN*DD;

    // device-global scratch pointers (for GEMM args)
    float *p_xn, *p_q, *p_k, *p_v, *p_agg, *p_x1, *p_h;
    cudaGetSymbolAddress((void**)&p_xn,  g_xn);
    cudaGetSymbolAddress((void**)&p_q,   g_q);
    cudaGetSymbolAddress((void**)&p_k,   g_k);
    cudaGetSymbolAddress((void**)&p_v,   g_v);
    cudaGetSymbolAddress((void**)&p_agg, g_agg);
    cudaGetSymbolAddress((void**)&p_x1,  g_x1);
    cudaGetSymbolAddress((void**)&p_h,   g_h);

    const int eblocks = (NE + 7) / 8;                 // 8 edges (warps)/block

    // 0. zero accumulators
    zero_kernel<<<(NN*DD + 255) / 256, 256>>>();

    // 1. LN1
    ln_kernel<<<NN, 256>>>(x, g1, be1, p_xn);

    // 2-4. q, k, v projections
    dim3 gqkv(DD / BN, (NN + BM - 1) / BM);
    sgemm_kernel<0><<<gqkv, 256>>>(p_xn, Wq, bq, p_q, NN, DD, DD, nullptr, nullptr);
    sgemm_kernel<0><<<gqkv, 256>>>(p_xn, Wk, bk, p_k, NN, DD, DD, nullptr, nullptr);
    sgemm_kernel<0><<<gqkv, 256>>>(p_xn, Wv, bv, p_v, NN, DD, DD, nullptr, nullptr);

    // 5. edge projection
    ep_kernel<<<eblocks, 256>>>(ef, We, be);

    // 6. scores + segment max
    scores_kernel<<<eblocks, 256>>>(ei, ew);

    // 7. exp + segment sum
    expsum_kernel<<<(NE*HH + 255) / 256, 256>>>(ei);

    // 8. normalize, emit attn weights, scatter-aggregate
    agg_kernel<<<eblocks, 256>>>(ei, out_attn);

    // 9. attn out projection + residual (x1 = x + alpha * (agg @ Wo^T + bo))
    sgemm_kernel<1><<<gqkv, 256>>>(p_agg, Wo, bo, p_x1, NN, DD, DD, x, alpha);

    // 10. LN2
    ln_kernel<<<NN, 256>>>(p_x1, g2, be2, p_xn);

    // 11. FFN up + GELU
    dim3 gffn1(D4 / BN, (NN + BM - 1) / BM);
    sgemm_kernel<2><<<gffn1, 256>>>(p_xn, W1, b1, p_h, NN, D4, DD, nullptr, nullptr);

    // 12. FFN down + residual -> final x directly into d_out
    sgemm_kernel<1><<<gqkv, 256>>>(p_h, W2, b2, out_x, NN, DD, D4, p_x1, beta);
}

// round 6
// speedup vs baseline: 1.1546x; 1.1546x over previous
#include <cuda_runtime.h>
#include <cuda_bf16.h>
#include <mma.h>
#include <math.h>
#include <stdint.h>

using namespace nvcuda;

#define NN 50000
#define NE 1600000
#define DD 256
#define HH 8
#define HDIM 32
#define EDIM 32
#define D4 (4*DD)

// ---------------- scratch (device globals; no runtime allocation) ----------
__device__ float    g_xn[(size_t)NN*DD];
__device__ float    g_q [(size_t)NN*DD];
__device__ float    g_k [(size_t)NN*DD];
__device__ float    g_v [(size_t)NN*DD];
__device__ float    g_ep[(size_t)NE*HDIM];
__device__ float    g_scores[(size_t)NE*HH];
__device__ unsigned g_smax[(size_t)NN*HH];
__device__ float    g_ssum[(size_t)NN*HH];
__device__ float    g_agg[(size_t)NN*DD];
__device__ float    g_x1 [(size_t)NN*DD];
__device__ float    g_h  [(size_t)NN*D4];

// order-preserving float->uint encode for atomicMax
__device__ __forceinline__ unsigned fenc(float f) {
    unsigned u = __float_as_uint(f);
    return (u & 0x80000000u) ? ~u : (u | 0x80000000u);
}
__device__ __forceinline__ float fdec(unsigned u) {
    return (u & 0x80000000u) ? __uint_as_float(u & 0x7fffffffu)
                             : __uint_as_float(~u);
}

__device__ __forceinline__ uint32_t pack_bf2(__nv_bfloat16 a, __nv_bfloat16 b) {
    return (uint32_t)__bfloat16_as_ushort(a) | ((uint32_t)__bfloat16_as_ushort(b) << 16);
}
__device__ __forceinline__ void cvt_hilo(float4 v, uint2& hi, uint2& lo) {
    __nv_bfloat16 hx = __float2bfloat16(v.x);
    __nv_bfloat16 hy = __float2bfloat16(v.y);
    __nv_bfloat16 hz = __float2bfloat16(v.z);
    __nv_bfloat16 hw = __float2bfloat16(v.w);
    __nv_bfloat16 lx = __float2bfloat16(v.x - __bfloat162float(hx));
    __nv_bfloat16 ly = __float2bfloat16(v.y - __bfloat162float(hy));
    __nv_bfloat16 lz = __float2bfloat16(v.z - __bfloat162float(hz));
    __nv_bfloat16 lw = __float2bfloat16(v.w - __bfloat162float(hw));
    hi.x = pack_bf2(hx, hy); hi.y = pack_bf2(hz, hw);
    lo.x = pack_bf2(lx, ly); lo.y = pack_bf2(lz, lw);
}

__device__ __forceinline__ float gelu_exact(float x) {
    return 0.5f * x * (1.0f + erff(x * 0.70710678118654752f));
}

// ============== wmma bf16 hi/lo GEMM: C = act(A[M,K] @ B[N,K]^T + bias) ====
// MODE 0: plain; MODE 1: C = res + scale*val; MODE 2: exact GELU
// Block tile 128x128, BK=32, 8 warps (warp tile 64x32).
// SMEM bf16 tiles have leading dim 40 (80 B rows): LDSM conflict-free.
#define LDT 40
#define TILEB (128*LDT*2)            // 10240 B per bf16 tile
#define BUFB  (4*TILEB)              // Ahi,Alo,Bhi,Blo = 40960 B
#define GEMM_SMEM (2*BUFB)           // 81920 B (also covers 128*132*4 epilogue)

template<int MODE>
__global__ void __launch_bounds__(256)
tc_gemm(const float* __restrict__ A, const float* __restrict__ B,
        const float* __restrict__ bias, float* __restrict__ C,
        int M, int N, int K,
        const float* __restrict__ res, const float* __restrict__ scalep)
{
    extern __shared__ char smem[];
    const int tid = threadIdx.x;
    const int bm = blockIdx.y * 128;
    const int bn = blockIdx.x * 128;
    const int warp = tid >> 5;
    const int wm = (warp >> 2) * 64;   // 0 or 64
    const int wn = (warp & 3) * 32;    // 0,32,64,96

    wmma::fragment<wmma::accumulator, 16, 16, 16, float> fc[4][2];
    #pragma unroll
    for (int i = 0; i < 4; i++)
        #pragma unroll
        for (int j = 0; j < 2; j++)
            wmma::fill_fragment(fc[i][j], 0.0f);

    const int nch = K >> 5;
    float4 ra[4], rb[4];

    // prefetch chunk 0
    {
        const float* Ac = A + (size_t)bm * K;
        const float* Bc = B + (size_t)bn * K;
        #pragma unroll
        for (int i = 0; i < 4; i++) {
            int s = tid + i*256;
            int row = s >> 3, c4 = (s & 7) << 2;
            ra[i] = (bm + row < M) ? *(const float4*)(Ac + (size_t)row*K + c4)
                                   : make_float4(0.f,0.f,0.f,0.f);
            rb[i] = *(const float4*)(Bc + (size_t)row*K + c4);
        }
    }
    // store chunk 0 into buf 0
    {
        char* base = smem;
        #pragma unroll
        for (int i = 0; i < 4; i++) {
            int s = tid + i*256;
            int row = s >> 3, c4 = (s & 7) << 2;
            int off = (row*LDT + c4) * 2;
            uint2 hi, lo;
            cvt_hilo(ra[i], hi, lo);
            *(uint2*)(base + off)           = hi;
            *(uint2*)(base + TILEB + off)   = lo;
            cvt_hilo(rb[i], hi, lo);
            *(uint2*)(base + 2*TILEB + off) = hi;
            *(uint2*)(base + 3*TILEB + off) = lo;
        }
    }
    __syncthreads();

    for (int kc = 0; kc < nch; kc++) {
        if (kc + 1 < nch) {
            const float* Ac = A + (size_t)bm * K + (kc+1)*32;
            const float* Bc = B + (size_t)bn * K + (kc+1)*32;
            #pragma unroll
            for (int i = 0; i < 4; i++) {
                int s = tid + i*256;
                int row = s >> 3, c4 = (s & 7) << 2;
                ra[i] = (bm + row < M) ? *(const float4*)(Ac + (size_t)row*K + c4)
                                       : make_float4(0.f,0.f,0.f,0.f);
                rb[i] = *(const float4*)(Bc + (size_t)row*K + c4);
            }
        }

        const char* base = smem + (kc & 1) * BUFB;
        const __nv_bfloat16* pAh = (const __nv_bfloat16*)(base);
        const __nv_bfloat16* pAl = (const __nv_bfloat16*)(base + TILEB);
        const __nv_bfloat16* pBh = (const __nv_bfloat16*)(base + 2*TILEB);
        const __nv_bfloat16* pBl = (const __nv_bfloat16*)(base + 3*TILEB);

        #pragma unroll
        for (int ks = 0; ks < 32; ks += 16) {
            wmma::fragment<wmma::matrix_a, 16, 16, 16, __nv_bfloat16, wmma::row_major> fah[4], fal[4];
            wmma::fragment<wmma::matrix_b, 16, 16, 16, __nv_bfloat16, wmma::col_major> fbh[2], fbl[2];
            #pragma unroll
            for (int i = 0; i < 4; i++) {
                wmma::load_matrix_sync(fah[i], pAh + (wm + 16*i)*LDT + ks, LDT);
                wmma::load_matrix_sync(fal[i], pAl + (wm + 16*i)*LDT + ks, LDT);
            }
            #pragma unroll
            for (int j = 0; j < 2; j++) {
                wmma::load_matrix_sync(fbh[j], pBh + (wn + 16*j)*LDT + ks, LDT);
                wmma::load_matrix_sync(fbl[j], pBl + (wn + 16*j)*LDT + ks, LDT);
            }
            #pragma unroll
            for (int i = 0; i < 4; i++)
                #pragma unroll
                for (int j = 0; j < 2; j++) {
                    wmma::mma_sync(fc[i][j], fah[i], fbh[j], fc[i][j]);
                    wmma::mma_sync(fc[i][j], fah[i], fbl[j], fc[i][j]);
                    wmma::mma_sync(fc[i][j], fal[i], fbh[j], fc[i][j]);
                }
        }

        if (kc + 1 < nch) {
            char* nb = smem + ((kc+1) & 1) * BUFB;
            #pragma unroll
            for (int i = 0; i < 4; i++) {
                int s = tid + i*256;
                int row = s >> 3, c4 = (s & 7) << 2;
                int off = (row*LDT + c4) * 2;
                uint2 hi, lo;
                cvt_hilo(ra[i], hi, lo);
                *(uint2*)(nb + off)           = hi;
                *(uint2*)(nb + TILEB + off)   = lo;
                cvt_hilo(rb[i], hi, lo);
                *(uint2*)(nb + 2*TILEB + off) = hi;
                *(uint2*)(nb + 3*TILEB + off) = lo;
            }
        }
        __syncthreads();
    }

    // ---- epilogue through SMEM ----
    float* Cs = (float*)smem;    // 128 x 132
    #pragma unroll
    for (int i = 0; i < 4; i++)
        #pragma unroll
        for (int j = 0; j < 2; j++)
            wmma::store_matrix_sync(Cs + (wm + 16*i)*132 + wn + 16*j, fc[i][j],
                                    132, wmma::mem_row_major);
    __syncthreads();

    const float scale = (MODE == 1) ? scalep[0] : 1.0f;
    int row = tid >> 1;
    int cbase = (tid & 1) * 64;
    int m = bm + row;
    if (m < M) {
        #pragma unroll
        for (int j = 0; j < 64; j += 4) {
            int n = bn + cbase + j;
            float4 v = *(float4*)(Cs + row*132 + cbase + j);
            float4 bi = *(const float4*)(bias + n);
            v.x += bi.x; v.y += bi.y; v.z += bi.z; v.w += bi.w;
            if (MODE == 2) {
                v.x = gelu_exact(v.x); v.y = gelu_exact(v.y);
                v.z = gelu_exact(v.z); v.w = gelu_exact(v.w);
            }
            if (MODE == 1) {
                float4 r = *(const float4*)(res + (size_t)m*N + n);
                v.x = r.x + scale*v.x; v.y = r.y + scale*v.y;
                v.z = r.z + scale*v.z; v.w = r.w + scale*v.w;
            }
            *(float4*)(C + (size_t)m*N + n) = v;
        }
    }
}

// ---------------- zero init (agg, ssum, smax) ------------------------------
__global__ void zero_kernel() {
    int i = blockIdx.x * blockDim.x + threadIdx.x;
    if (i < NN*DD) g_agg[i] = 0.f;
    if (i < NN*HH) { g_ssum[i] = 0.f; g_smax[i] = 0u; }
}

// ---------------- layernorm: one block (256 thr) per row -------------------
__global__ void ln_kernel(const float* __restrict__ in,
                          const float* __restrict__ g,
                          const float* __restrict__ b,
                          float* __restrict__ out) {
    int row = blockIdx.x;
    int t = threadIdx.x;
    float v = in[(size_t)row*DD + t];
    float s = v, s2 = v*v;
    #pragma unroll
    for (int off = 16; off; off >>= 1) {
        s  += __shfl_xor_sync(0xffffffffu, s,  off);
        s2 += __shfl_xor_sync(0xffffffffu, s2, off);
    }
    __shared__ float ws[8], ws2[8], mustd[2];
    int w = t >> 5, lane = t & 31;
    if (lane == 0) { ws[w] = s; ws2[w] = s2; }
    __syncthreads();
    if (t == 0) {
        float ts = 0.f, ts2 = 0.f;
        #pragma unroll
        for (int i = 0; i < 8; i++) { ts += ws[i]; ts2 += ws2[i]; }
        float mu = ts * (1.0f/DD);
        float var = ts2 * (1.0f/DD) - mu*mu;
        mustd[0] = mu;
        mustd[1] = 1.0f / sqrtf(var + 1e-5f);
    }
    __syncthreads();
    out[(size_t)row*DD + t] = (v - mustd[0]) * mustd[1] * g[t] + b[t];
}

// ---------------- edge projection: ep[E,32] = ef[E,32] @ We[32,32]^T + be --
__global__ __launch_bounds__(256)
void ep_kernel(const float* __restrict__ ef, const float* __restrict__ We,
               const float* __restrict__ be) {
    __shared__ float WeT[EDIM][HDIM+1];
    __shared__ float bsh[HDIM];
    int tid = threadIdx.x;
    for (int i = tid; i < HDIM*EDIM; i += 256) {
        int r = i / EDIM, c = i % EDIM;
        WeT[c][r] = We[i];
    }
    if (tid < HDIM) bsh[tid] = be[tid];
    __syncthreads();
    int warp = tid >> 5, lane = tid & 31;
    size_t e = (size_t)blockIdx.x * 8 + warp;
    if (e >= NE) return;
    float f = ef[e*EDIM + lane];
    float acc = bsh[lane];
    #pragma unroll
    for (int k2 = 0; k2 < EDIM; k2++) {
        float fk = __shfl_sync(0xffffffffu, f, k2);
        acc = fmaf(fk, WeT[k2][lane], acc);
    }
    g_ep[e*HDIM + lane] = acc;
}

// ---------------- per-edge scores + segment max ----------------------------
__global__ __launch_bounds__(256)
void scores_kernel(const int* __restrict__ ei, const float* __restrict__ ew) {
    int lane = threadIdx.x & 31;
    size_t e = (size_t)blockIdx.x * 8 + (threadIdx.x >> 5);
    if (e >= NE) return;
    int src = ei[e];
    int dst = ei[NE + e];
    float epv = g_ep[e*HDIM + lane];
    const float* qr = g_q + (size_t)dst*DD + lane;
    const float* kr = g_k + (size_t)src*DD + lane;
    float acc[HH];
    #pragma unroll
    for (int h = 0; h < HH; h++)
        acc[h] = qr[h*HDIM] * (kr[h*HDIM] + epv);
    #pragma unroll
    for (int off = 16; off; off >>= 1)
        #pragma unroll
        for (int h = 0; h < HH; h++)
            acc[h] += __shfl_xor_sync(0xffffffffu, acc[h], off);
    if (lane == 0) {
        float w = ew[e] * 0.17677669529663687f;
        #pragma unroll
        for (int h = 0; h < HH; h++) {
            float s = acc[h] * w;
            g_scores[e*HH + h] = s;
            atomicMax(&g_smax[dst*HH + h], fenc(s));
        }
    }
}

// ---------------- exp(score - max) + segment sum (in place) ----------------
__global__ void expsum_kernel(const int* __restrict__ ei) {
    int i = blockIdx.x * blockDim.x + threadIdx.x;
    if (i >= NE*HH) return;
    int e = i >> 3;
    int h = i & 7;
    int dst = ei[NE + e];
    float m = fdec(g_smax[dst*HH + h]);
    float v = expf(g_scores[i] - m);
    g_scores[i] = v;
    atomicAdd(&g_ssum[dst*HH + h], v);
}

// ---------------- normalize + weighted scatter aggregate -------------------
__global__ __launch_bounds__(256)
void agg_kernel(const int* __restrict__ ei, float* __restrict__ attn_out) {
    int lane = threadIdx.x & 31;
    size_t e = (size_t)blockIdx.x * 8 + (threadIdx.x >> 5);
    if (e >= NE) return;
    int src = ei[e];
    int dst = ei[NE + e];
    float w = 0.f;
    if (lane < HH) {
        w = g_scores[e*HH + lane] / g_ssum[dst*HH + lane];
        if (attn_out) attn_out[e*HH + lane] = w;
    }
    float wh[HH];
    #pragma unroll
    for (int h = 0; h < HH; h++)
        wh[h] = __shfl_sync(0xffffffffu, w, h);
    const float* vr = g_v + (size_t)src*DD + lane;
    float* ar = g_agg + (size_t)dst*DD + lane;
    #pragma unroll
    for (int h = 0; h < HH; h++)
        atomicAdd(ar + h*HDIM, wh[h] * vr[h*HDIM]);
}

// ---------------------------------------------------------------------------
extern "C" void kernel_launch(void* const* d_in, const int* in_sizes, int n_in,
                              void* d_out, int out_size) {
    const float* x     = (const float*)d_in[0];
    const int*   ei    = (const int*)  d_in[1];
    const float* ef    = (const float*)d_in[2];
    const float* ew    = (const float*)d_in[3];
    const float* Wq    = (const float*)d_in[4];
    const float* bq    = (const float*)d_in[5];
    const float* Wk    = (const float*)d_in[6];
    const float* bk    = (const float*)d_in[7];
    const float* Wv    = (const float*)d_in[8];
    const float* bv    = (const float*)d_in[9];
    const float* We    = (const float*)d_in[10];
    const float* be    = (const float*)d_in[11];
    const float* Wo    = (const float*)d_in[12];
    const float* bo    = (const float*)d_in[13];
    const float* W1    = (const float*)d_in[14];
    const float* b1    = (const float*)d_in[15];
    const float* W2    = (const float*)d_in[16];
    const float* b2    = (const float*)d_in[17];
    const float* g1    = (const float*)d_in[18];
    const float* be1   = (const float*)d_in[19];
    const float* g2    = (const float*)d_in[20];
    const float* be2   = (const float*)d_in[21];
    const float* alpha = (const float*)d_in[22];
    const float* beta  = (const float*)d_in[23];

    float* out = (float*)d_out;
    float* out_x = out;
    float* out_attn = nullptr;
    if (out_size >= NN*DD + NE*HH) out_attn = out + (size_t)NN*DD;

    float *p_xn, *p_q, *p_k, *p_v, *p_agg, *p_x1, *p_h;
    cudaGetSymbolAddress((void**)&p_xn,  g_xn);
    cudaGetSymbolAddress((void**)&p_q,   g_q);
    cudaGetSymbolAddress((void**)&p_k,   g_k);
    cudaGetSymbolAddress((void**)&p_v,   g_v);
    cudaGetSymbolAddress((void**)&p_agg, g_agg);
    cudaGetSymbolAddress((void**)&p_x1,  g_x1);
    cudaGetSymbolAddress((void**)&p_h,   g_h);

    cudaFuncSetAttribute(tc_gemm<0>, cudaFuncAttributeMaxDynamicSharedMemorySize, GEMM_SMEM);
    cudaFuncSetAttribute(tc_gemm<1>, cudaFuncAttributeMaxDynamicSharedMemorySize, GEMM_SMEM);
    cudaFuncSetAttribute(tc_gemm<2>, cudaFuncAttributeMaxDynamicSharedMemorySize, GEMM_SMEM);

    const int eblocks = (NE + 7) / 8;
    const int mtiles = (NN + 127) / 128;   // 391

    // 0. zero accumulators
    zero_kernel<<<(NN*DD + 255) / 256, 256>>>();

    // 1. LN1
    ln_kernel<<<NN, 256>>>(x, g1, be1, p_xn);

    // 2-4. q, k, v projections (HMMA bf16 hi/lo)
    dim3 g256(DD/128, mtiles);
    tc_gemm<0><<<g256, 256, GEMM_SMEM>>>(p_xn, Wq, bq, p_q, NN, DD, DD, nullptr, nullptr);
    tc_gemm<0><<<g256, 256, GEMM_SMEM>>>(p_xn, Wk, bk, p_k, NN, DD, DD, nullptr, nullptr);
    tc_gemm<0><<<g256, 256, GEMM_SMEM>>>(p_xn, Wv, bv, p_v, NN, DD, DD, nullptr, nullptr);

    // 5. edge projection
    ep_kernel<<<eblocks, 256>>>(ef, We, be);

    // 6. scores + segment max
    scores_kernel<<<eblocks, 256>>>(ei, ew);

    // 7. exp + segment sum
    expsum_kernel<<<(NE*HH + 255) / 256, 256>>>(ei);

    // 8. normalize, emit attn weights, scatter-aggregate
    agg_kernel<<<eblocks, 256>>>(ei, out_attn);

    // 9. attn out projection + residual
    tc_gemm<1><<<g256, 256, GEMM_SMEM>>>(p_agg, Wo, bo, p_x1, NN, DD, DD, x, alpha);

    // 10. LN2
    ln_kernel<<<NN, 256>>>(p_x1, g2, be2, p_xn);

    // 11. FFN up + GELU
    dim3 g1024(D4/128, mtiles);
    tc_gemm<2><<<g1024, 256, GEMM_SMEM>>>(p_xn, W1, b1, p_h, NN, D4, DD, nullptr, nullptr);

    // 12. FFN down + residual -> final x into d_out
    tc_gemm<1><<<g256, 256, GEMM_SMEM>>>(p_h, W2, b2, out_x, NN, DD, D4, p_x1, beta);
}

// round 10
// speedup vs baseline: 1.4803x; 1.2821x over previous
#include <cuda_runtime.h>
#include <cuda_bf16.h>
#include <mma.h>
#include <math.h>
#include <stdint.h>

using namespace nvcuda;

#define NN 50000
#define NE 1600000
#define DD 256
#define HH 8
#define HDIM 32
#define EDIM 32
#define D4 (4*DD)

// ---------------- scratch (device globals; no runtime allocation) ----------
__device__ float    g_q [(size_t)NN*DD];
__device__ float    g_k [(size_t)NN*DD];
__device__ float    g_v [(size_t)NN*DD];
__device__ float    g_ep[(size_t)NE*HDIM];
__device__ float    g_scores[(size_t)NE*HH];
__device__ unsigned g_smax[(size_t)NN*HH];
__device__ float    g_ssum[(size_t)NN*HH];
__device__ float    g_agg[(size_t)NN*DD];
__device__ float    g_x1 [(size_t)NN*DD];
// bf16 hi/lo operand arrays
__device__ __nv_bfloat16 g_xnh[(size_t)NN*DD];
__device__ __nv_bfloat16 g_xnl[(size_t)NN*DD];
__device__ __nv_bfloat16 g_aggh[(size_t)NN*DD];
__device__ __nv_bfloat16 g_aggl[(size_t)NN*DD];
__device__ __nv_bfloat16 g_hh[(size_t)NN*D4];
__device__ __nv_bfloat16 g_hl[(size_t)NN*D4];
// all weights packed: Wq,Wk,Wv,Wo (65536 each), W1 (262144), W2 (262144)
#define WQO 0
#define WKO 65536
#define WVO 131072
#define WOO 196608
#define W1O 262144
#define W2O 524288
#define WTOT 786432
__device__ __nv_bfloat16 g_wh[WTOT];
__device__ __nv_bfloat16 g_wl[WTOT];

// ---------------- small helpers -------------------------------------------
__device__ __forceinline__ unsigned fenc(float f) {
    unsigned u = __float_as_uint(f);
    return (u & 0x80000000u) ? ~u : (u | 0x80000000u);
}
__device__ __forceinline__ float fdec(unsigned u) {
    return (u & 0x80000000u) ? __uint_as_float(u & 0x7fffffffu)
                             : __uint_as_float(~u);
}
__device__ __forceinline__ uint32_t pack_bf2(__nv_bfloat16 a, __nv_bfloat16 b) {
    return (uint32_t)__bfloat16_as_ushort(a) | ((uint32_t)__bfloat16_as_ushort(b) << 16);
}
__device__ __forceinline__ void cvt_hilo(float4 v, uint2& hi, uint2& lo) {
    __nv_bfloat16 hx = __float2bfloat16(v.x);
    __nv_bfloat16 hy = __float2bfloat16(v.y);
    __nv_bfloat16 hz = __float2bfloat16(v.z);
    __nv_bfloat16 hw = __float2bfloat16(v.w);
    __nv_bfloat16 lx = __float2bfloat16(v.x - __bfloat162float(hx));
    __nv_bfloat16 ly = __float2bfloat16(v.y - __bfloat162float(hy));
    __nv_bfloat16 lz = __float2bfloat16(v.z - __bfloat162float(hz));
    __nv_bfloat16 lw = __float2bfloat16(v.w - __bfloat162float(hw));
    hi.x = pack_bf2(hx, hy); hi.y = pack_bf2(hz, hw);
    lo.x = pack_bf2(lx, ly); lo.y = pack_bf2(lz, lw);
}
__device__ __forceinline__ float gelu_exact(float x) {
    return 0.5f * x * (1.0f + erff(x * 0.70710678118654752f));
}
__device__ __forceinline__ uint32_t smem_u32(const void* p) {
    uint32_t a;
    asm("{ .reg .u64 t; cvta.to.shared.u64 t, %1; cvt.u32.u64 %0, t; }"
        : "=r"(a) : "l"(p));
    return a;
}
__device__ __forceinline__ void cpa16(uint32_t dst, const void* src, bool p) {
    int sz = p ? 16 : 0;
    asm volatile("cp.async.cg.shared.global [%0], [%1], 16, %2;"
                 :: "r"(dst), "l"(src), "r"(sz));
}
__device__ __forceinline__ void red4(float* p, float a, float b, float c, float d) {
    asm volatile("red.global.add.v4.f32 [%0], {%1, %2, %3, %4};"
                 :: "l"(p), "f"(a), "f"(b), "f"(c), "f"(d) : "memory");
}

// ============== bf16 hi/lo GEMM: C = act(A[M,K] @ B[N,K]^T + bias) =========
// A,B supplied as bf16 hi/lo pairs in global. cp.async double-buffered.
// MODE 0: C fp32; MODE 1: C = res + scale*(val+bias); MODE 2: GELU -> bf16 hi/lo
#define LDT 40
#define TILE_B (128*LDT*2)          // 10240 B
#define STAGE_B (4*TILE_B)          // 40960 B (Ahi,Alo,Bhi,Blo)
#define GEMM_SMEM (2*STAGE_B)       // 81920 B (also covers 128x132 fp32 epilogue)

__device__ __forceinline__ void stage_load(
    char* smem, int buf,
    const __nv_bfloat16* __restrict__ Ahi, const __nv_bfloat16* __restrict__ Alo,
    const __nv_bfloat16* __restrict__ Bhi, const __nv_bfloat16* __restrict__ Blo,
    int bm, int bn, int M, int K, int kc, int tid)
{
    uint32_t sb = smem_u32(smem) + buf * STAGE_B;
    #pragma unroll
    for (int j = 0; j < 2; j++) {
        int idx = tid + j*256;               // 0..511 chunks of 16B
        int row = idx >> 2;                  // 0..127
        int c   = (idx & 3) * 8;             // bf16 column
        uint32_t soff = (uint32_t)(row*LDT + c) * 2;
        size_t gA = (size_t)(bm + row) * K + kc*32 + c;
        size_t gB = (size_t)(bn + row) * K + kc*32 + c;
        bool pa = (bm + row) < M;
        cpa16(sb + soff,              pa ? (const void*)(Ahi + gA) : (const void*)Ahi, pa);
        cpa16(sb + TILE_B + soff,     pa ? (const void*)(Alo + gA) : (const void*)Alo, pa);
        cpa16(sb + 2*TILE_B + soff,   Bhi + gB, true);
        cpa16(sb + 3*TILE_B + soff,   Blo + gB, true);
    }
    asm volatile("cp.async.commit_group;" ::: "memory");
}

template<int MODE>
__global__ void __launch_bounds__(256, 2)
tc_gemm(const __nv_bfloat16* __restrict__ Ahi, const __nv_bfloat16* __restrict__ Alo,
        const __nv_bfloat16* __restrict__ Bhi, const __nv_bfloat16* __restrict__ Blo,
        const float* __restrict__ bias, float* __restrict__ C,
        __nv_bfloat16* __restrict__ Chi, __nv_bfloat16* __restrict__ Clo,
        int M, int N, int K,
        const float* __restrict__ res, const float* __restrict__ scalep)
{
    extern __shared__ char smem[];
    const int tid = threadIdx.x;
    const int bm = blockIdx.y * 128;
    const int bn = blockIdx.x * 128;
    const int warp = tid >> 5;
    const int wm = (warp >> 2) * 64;
    const int wn = (warp & 3) * 32;

    wmma::fragment<wmma::accumulator, 16, 16, 16, float> fc[4][2];
    #pragma unroll
    for (int i = 0; i < 4; i++)
        #pragma unroll
        for (int j = 0; j < 2; j++)
            wmma::fill_fragment(fc[i][j], 0.0f);

    const int nch = K >> 5;
    stage_load(smem, 0, Ahi, Alo, Bhi, Blo, bm, bn, M, K, 0, tid);
    if (nch > 1) stage_load(smem, 1, Ahi, Alo, Bhi, Blo, bm, bn, M, K, 1, tid);

    for (int kc = 0; kc < nch; kc++) {
        if (kc + 1 < nch) asm volatile("cp.async.wait_group 1;" ::: "memory");
        else              asm volatile("cp.async.wait_group 0;" ::: "memory");
        __syncthreads();

        const char* base = smem + (kc & 1) * STAGE_B;
        const __nv_bfloat16* pAh = (const __nv_bfloat16*)(base);
        const __nv_bfloat16* pAl = (const __nv_bfloat16*)(base + TILE_B);
        const __nv_bfloat16* pBh = (const __nv_bfloat16*)(base + 2*TILE_B);
        const __nv_bfloat16* pBl = (const __nv_bfloat16*)(base + 3*TILE_B);

        #pragma unroll
        for (int ks = 0; ks < 32; ks += 16) {
            wmma::fragment<wmma::matrix_b, 16, 16, 16, __nv_bfloat16, wmma::col_major> fbh[2], fbl[2];
            #pragma unroll
            for (int j = 0; j < 2; j++) {
                wmma::load_matrix_sync(fbh[j], pBh + (wn + 16*j)*LDT + ks, LDT);
                wmma::load_matrix_sync(fbl[j], pBl + (wn + 16*j)*LDT + ks, LDT);
            }
            #pragma unroll
            for (int i = 0; i < 4; i++) {
                wmma::fragment<wmma::matrix_a, 16, 16, 16, __nv_bfloat16, wmma::row_major> fah, fal;
                wmma::load_matrix_sync(fah, pAh + (wm + 16*i)*LDT + ks, LDT);
                wmma::load_matrix_sync(fal, pAl + (wm + 16*i)*LDT + ks, LDT);
                #pragma unroll
                for (int j = 0; j < 2; j++) {
                    wmma::mma_sync(fc[i][j], fah, fbh[j], fc[i][j]);
                    wmma::mma_sync(fc[i][j], fah, fbl[j], fc[i][j]);
                    wmma::mma_sync(fc[i][j], fal, fbh[j], fc[i][j]);
                }
            }
        }
        __syncthreads();
        if (kc + 2 < nch)
            stage_load(smem, kc & 1, Ahi, Alo, Bhi, Blo, bm, bn, M, K, kc + 2, tid);
    }

    // ---- epilogue through SMEM ----
    float* Cs = (float*)smem;    // 128 x 132
    #pragma unroll
    for (int i = 0; i < 4; i++)
        #pragma unroll
        for (int j = 0; j < 2; j++)
            wmma::store_matrix_sync(Cs + (wm + 16*i)*132 + wn + 16*j, fc[i][j],
                                    132, wmma::mem_row_major);
    __syncthreads();

    const float scale = (MODE == 1) ? scalep[0] : 1.0f;
    int row = tid >> 1;
    int cbase = (tid & 1) * 64;
    int m = bm + row;
    if (m < M) {
        #pragma unroll
        for (int j = 0; j < 64; j += 4) {
            int n = bn + cbase + j;
            float4 v = *(float4*)(Cs + row*132 + cbase + j);
            float4 bi = *(const float4*)(bias + n);
            v.x += bi.x; v.y += bi.y; v.z += bi.z; v.w += bi.w;
            if (MODE == 2) {
                v.x = gelu_exact(v.x); v.y = gelu_exact(v.y);
                v.z = gelu_exact(v.z); v.w = gelu_exact(v.w);
                uint2 hi, lo;
                cvt_hilo(v, hi, lo);
                *(uint2*)(Chi + (size_t)m*N + n) = hi;
                *(uint2*)(Clo + (size_t)m*N + n) = lo;
            } else {
                if (MODE == 1) {
                    float4 r = *(const float4*)(res + (size_t)m*N + n);
                    v.x = r.x + scale*v.x; v.y = r.y + scale*v.y;
                    v.z = r.z + scale*v.z; v.w = r.w + scale*v.w;
                }
                *(float4*)(C + (size_t)m*N + n) = v;
            }
        }
    }
}

// ---------------- fp32 -> bf16 hi/lo convert -------------------------------
__global__ void cvt_kernel(const float* __restrict__ in,
                           __nv_bfloat16* __restrict__ hi,
                           __nv_bfloat16* __restrict__ lo, int n4) {
    int i = blockIdx.x * blockDim.x + threadIdx.x;
    if (i < n4) {
        float4 v = ((const float4*)in)[i];
        uint2 h, l;
        cvt_hilo(v, h, l);
        ((uint2*)hi)[i] = h;
        ((uint2*)lo)[i] = l;
    }
}

// ---------------- zero init (agg, ssum, smax) ------------------------------
__global__ void zero_kernel() {
    int i = blockIdx.x * blockDim.x + threadIdx.x;
    if (i < NN*DD) g_agg[i] = 0.f;
    if (i < NN*HH) { g_ssum[i] = 0.f; g_smax[i] = 0u; }
}

// ---------------- layernorm -> bf16 hi/lo ----------------------------------
__global__ void ln_kernel(const float* __restrict__ in,
                          const float* __restrict__ g,
                          const float* __restrict__ b,
                          __nv_bfloat16* __restrict__ out_hi,
                          __nv_bfloat16* __restrict__ out_lo) {
    int row = blockIdx.x;
    int t = threadIdx.x;
    float v = in[(size_t)row*DD + t];
    float s = v, s2 = v*v;
    #pragma unroll
    for (int off = 16; off; off >>= 1) {
        s  += __shfl_xor_sync(0xffffffffu, s,  off);
        s2 += __shfl_xor_sync(0xffffffffu, s2, off);
    }
    __shared__ float ws[8], ws2[8], mustd[2];
    int w = t >> 5, lane = t & 31;
    if (lane == 0) { ws[w] = s; ws2[w] = s2; }
    __syncthreads();
    if (t == 0) {
        float ts = 0.f, ts2 = 0.f;
        #pragma unroll
        for (int i = 0; i < 8; i++) { ts += ws[i]; ts2 += ws2[i]; }
        float mu = ts * (1.0f/DD);
        float var = ts2 * (1.0f/DD) - mu*mu;
        mustd[0] = mu;
        mustd[1] = 1.0f / sqrtf(var + 1e-5f);
    }
    __syncthreads();
    float y = (v - mustd[0]) * mustd[1] * g[t] + b[t];
    __nv_bfloat16 h = __float2bfloat16(y);
    out_hi[(size_t)row*DD + t] = h;
    out_lo[(size_t)row*DD + t] = __float2bfloat16(y - __bfloat162float(h));
}

// ---------------- edge projection: ep[E,32] = ef[E,32] @ We[32,32]^T + be --
__global__ __launch_bounds__(256)
void ep_kernel(const float* __restrict__ ef, const float* __restrict__ We,
               const float* __restrict__ be) {
    __shared__ float WeT[EDIM][HDIM+1];
    __shared__ float bsh[HDIM];
    int tid = threadIdx.x;
    for (int i = tid; i < HDIM*EDIM; i += 256) {
        int r = i / EDIM, c = i % EDIM;
        WeT[c][r] = We[i];
    }
    if (tid < HDIM) bsh[tid] = be[tid];
    __syncthreads();
    int warp = tid >> 5, lane = tid & 31;
    size_t e = (size_t)blockIdx.x * 8 + warp;
    if (e >= NE) return;
    float f = ef[e*EDIM + lane];
    float acc = bsh[lane];
    #pragma unroll
    for (int k2 = 0; k2 < EDIM; k2++) {
        float fk = __shfl_sync(0xffffffffu, f, k2);
        acc = fmaf(fk, WeT[k2][lane], acc);
    }
    g_ep[e*HDIM + lane] = acc;
}

// ---------------- per-edge scores + segment max ----------------------------
__global__ __launch_bounds__(256)
void scores_kernel(const int* __restrict__ ei, const float* __restrict__ ew) {
    int lane = threadIdx.x & 31;
    size_t e = (size_t)blockIdx.x * 8 + (threadIdx.x >> 5);
    if (e >= NE) return;
    int src = ei[e];
    int dst = ei[NE + e];
    float epv = g_ep[e*HDIM + lane];
    const float* qr = g_q + (size_t)dst*DD + lane;
    const float* kr = g_k + (size_t)src*DD + lane;
    float acc[HH];
    #pragma unroll
    for (int h = 0; h < HH; h++)
        acc[h] = qr[h*HDIM] * (kr[h*HDIM] + epv);
    #pragma unroll
    for (int off = 16; off; off >>= 1)
        #pragma unroll
        for (int h = 0; h < HH; h++)
            acc[h] += __shfl_xor_sync(0xffffffffu, acc[h], off);
    if (lane == 0) {
        float w = ew[e] * 0.17677669529663687f;
        #pragma unroll
        for (int h = 0; h < HH; h++) {
            float s = acc[h] * w;
            g_scores[e*HH + h] = s;
            atomicMax(&g_smax[dst*HH + h], fenc(s));
        }
    }
}

// ---------------- exp(score - max) + vectorized segment sum ----------------
__global__ void expsum_kernel(const int* __restrict__ ei) {
    int e = blockIdx.x * blockDim.x + threadIdx.x;
    if (e >= NE) return;
    int dst = ei[NE + e];
    const unsigned* mp = g_smax + (size_t)dst*HH;
    uint4 m0 = *(const uint4*)(mp);
    uint4 m1 = *(const uint4*)(mp + 4);
    float4 s0 = *(float4*)(g_scores + (size_t)e*HH);
    float4 s1 = *(float4*)(g_scores + (size_t)e*HH + 4);
    s0.x = expf(s0.x - fdec(m0.x)); s0.y = expf(s0.y - fdec(m0.y));
    s0.z = expf(s0.z - fdec(m0.z)); s0.w = expf(s0.w - fdec(m0.w));
    s1.x = expf(s1.x - fdec(m1.x)); s1.y = expf(s1.y - fdec(m1.y));
    s1.z = expf(s1.z - fdec(m1.z)); s1.w = expf(s1.w - fdec(m1.w));
    *(float4*)(g_scores + (size_t)e*HH)     = s0;
    *(float4*)(g_scores + (size_t)e*HH + 4) = s1;
    float* sp = g_ssum + (size_t)dst*HH;
    red4(sp,     s0.x, s0.y, s0.z, s0.w);
    red4(sp + 4, s1.x, s1.y, s1.z, s1.w);
}

// ---------------- normalize + vectorized scatter aggregate -----------------
__global__ __launch_bounds__(256)
void agg_kernel(const int* __restrict__ ei, float* __restrict__ attn_out) {
    int lane = threadIdx.x & 31;
    size_t e = (size_t)blockIdx.x * 8 + (threadIdx.x >> 5);
    if (e >= NE) return;
    int src = ei[e];
    int dst = ei[NE + e];
    float w = 0.f;
    if (lane < HH) {
        w = g_scores[e*HH + lane] / g_ssum[(size_t)dst*HH + lane];
        if (attn_out) attn_out[e*HH + lane] = w;
    }
    float w0 = __shfl_sync(0xffffffffu, w, lane >> 3);
    float w1 = __shfl_sync(0xffffffffu, w, 4 + (lane >> 3));
    const float4* vr = (const float4*)(g_v + (size_t)src*DD);
    float* ar = g_agg + (size_t)dst*DD;
    float4 v0 = vr[lane];
    float4 v1 = vr[lane + 32];
    red4(ar + 4*lane,       w0*v0.x, w0*v0.y, w0*v0.z, w0*v0.w);
    red4(ar + 128 + 4*lane, w1*v1.x, w1*v1.y, w1*v1.z, w1*v1.w);
}

// ---------------------------------------------------------------------------
extern "C" void kernel_launch(void* const* d_in, const int* in_sizes, int n_in,
                              void* d_out, int out_size) {
    const float* x     = (const float*)d_in[0];
    const int*   ei    = (const int*)  d_in[1];
    const float* ef    = (const float*)d_in[2];
    const float* ew    = (const float*)d_in[3];
    const float* Wq    = (const float*)d_in[4];
    const float* bq    = (const float*)d_in[5];
    const float* Wk    = (const float*)d_in[6];
    const float* bk    = (const float*)d_in[7];
    const float* Wv    = (const float*)d_in[8];
    const float* bv    = (const float*)d_in[9];
    const float* We    = (const float*)d_in[10];
    const float* be    = (const float*)d_in[11];
    const float* Wo    = (const float*)d_in[12];
    const float* bo    = (const float*)d_in[13];
    const float* W1    = (const float*)d_in[14];
    const float* b1    = (const float*)d_in[15];
    const float* W2    = (const float*)d_in[16];
    const float* b2    = (const float*)d_in[17];
    const float* g1    = (const float*)d_in[18];
    const float* be1   = (const float*)d_in[19];
    const float* g2    = (const float*)d_in[20];
    const float* be2   = (const float*)d_in[21];
    const float* alpha = (const float*)d_in[22];
    const float* beta  = (const float*)d_in[23];

    float* out = (float*)d_out;
    float* out_x = out;
    float* out_attn = nullptr;
    if (out_size >= NN*DD + NE*HH) out_attn = out + (size_t)NN*DD;

    float *p_q, *p_k, *p_v, *p_agg, *p_x1;
    __nv_bfloat16 *p_xnh, *p_xnl, *p_aggh, *p_aggl, *p_hh, *p_hl, *p_wh, *p_wl;
    cudaGetSymbolAddress((void**)&p_q,    g_q);
    cudaGetSymbolAddress((void**)&p_k,    g_k);
    cudaGetSymbolAddress((void**)&p_v,    g_v);
    cudaGetSymbolAddress((void**)&p_agg,  g_agg);
    cudaGetSymbolAddress((void**)&p_x1,   g_x1);
    cudaGetSymbolAddress((void**)&p_xnh,  g_xnh);
    cudaGetSymbolAddress((void**)&p_xnl,  g_xnl);
    cudaGetSymbolAddress((void**)&p_aggh, g_aggh);
    cudaGetSymbolAddress((void**)&p_aggl, g_aggl);
    cudaGetSymbolAddress((void**)&p_hh,   g_hh);
    cudaGetSymbolAddress((void**)&p_hl,   g_hl);
    cudaGetSymbolAddress((void**)&p_wh,   g_wh);
    cudaGetSymbolAddress((void**)&p_wl,   g_wl);

    cudaFuncSetAttribute(tc_gemm<0>, cudaFuncAttributeMaxDynamicSharedMemorySize, GEMM_SMEM);
    cudaFuncSetAttribute(tc_gemm<1>, cudaFuncAttributeMaxDynamicSharedMemorySize, GEMM_SMEM);
    cudaFuncSetAttribute(tc_gemm<2>, cudaFuncAttributeMaxDynamicSharedMemorySize, GEMM_SMEM);

    const int eblocks = (NE + 7) / 8;
    const int mtiles = (NN + 127) / 128;   // 391

    // 0. zero accumulators
    zero_kernel<<<(NN*DD + 255) / 256, 256>>>();

    // 0b. convert weights to bf16 hi/lo (packed)
    cvt_kernel<<<64, 256>>>(Wq, p_wh + WQO, p_wl + WQO, 65536/4);
    cvt_kernel<<<64, 256>>>(Wk, p_wh + WKO, p_wl + WKO, 65536/4);
    cvt_kernel<<<64, 256>>>(Wv, p_wh + WVO, p_wl + WVO, 65536/4);
    cvt_kernel<<<64, 256>>>(Wo, p_wh + WOO, p_wl + WOO, 65536/4);
    cvt_kernel<<<256, 256>>>(W1, p_wh + W1O, p_wl + W1O, 262144/4);
    cvt_kernel<<<256, 256>>>(W2, p_wh + W2O, p_wl + W2O, 262144/4);

    // 1. LN1 -> bf16 hi/lo
    ln_kernel<<<NN, 256>>>(x, g1, be1, p_xnh, p_xnl);

    // 2-4. q, k, v projections
    dim3 g256(DD/128, mtiles);
    tc_gemm<0><<<g256, 256, GEMM_SMEM>>>(p_xnh, p_xnl, p_wh + WQO, p_wl + WQO,
                                         bq, p_q, nullptr, nullptr, NN, DD, DD, nullptr, nullptr);
    tc_gemm<0><<<g256, 256, GEMM_SMEM>>>(p_xnh, p_xnl, p_wh + WKO, p_wl + WKO,
                                         bk, p_k, nullptr, nullptr, NN, DD, DD, nullptr, nullptr);
    tc_gemm<0><<<g256, 256, GEMM_SMEM>>>(p_xnh, p_xnl, p_wh + WVO, p_wl + WVO,
                                         bv, p_v, nullptr, nullptr, NN, DD, DD, nullptr, nullptr);

    // 5. edge projection
    ep_kernel<<<eblocks, 256>>>(ef, We, be);

    // 6. scores + segment max
    scores_kernel<<<eblocks, 256>>>(ei, ew);

    // 7. exp + segment sum (one thread per edge, vec4 red)
    expsum_kernel<<<(NE + 255) / 256, 256>>>(ei);

    // 8. normalize, emit attn weights, scatter-aggregate (vec4 red)
    agg_kernel<<<eblocks, 256>>>(ei, out_attn);

    // 8b. convert agg to bf16 hi/lo
    cvt_kernel<<<(NN*DD/4 + 255) / 256, 256>>>(p_agg, p_aggh, p_aggl, NN*DD/4);

    // 9. attn out projection + residual
    tc_gemm<1><<<g256, 256, GEMM_SMEM>>>(p_aggh, p_aggl, p_wh + WOO, p_wl + WOO,
                                         bo, p_x1, nullptr, nullptr, NN, DD, DD, x, alpha);

    // 10. LN2 -> bf16 hi/lo
    ln_kernel<<<NN, 256>>>(p_x1, g2, be2, p_xnh, p_xnl);

    // 11. FFN up + GELU -> bf16 hi/lo h
    dim3 g1024(D4/128, mtiles);
    tc_gemm<2><<<g1024, 256, GEMM_SMEM>>>(p_xnh, p_xnl, p_wh + W1O, p_wl + W1O,
                                          b1, nullptr, p_hh, p_hl, NN, D4, DD, nullptr, nullptr);

    // 12. FFN down + residual -> final x into d_out
    tc_gemm<1><<<g256, 256, GEMM_SMEM>>>(p_hh, p_hl, p_wh + W2O, p_wl + W2O,
                                         b2, out_x, nullptr, nullptr, NN, DD, D4, p_x1, beta);
}

// round 11
// speedup vs baseline: 1.5100x; 1.0200x over previous
#include <cuda_runtime.h>
#include <cuda_bf16.h>
#include <mma.h>
#include <math.h>
#include <stdint.h>

using namespace nvcuda;

#define NN 50000
#define NE 1600000
#define DD 256
#define HH 8
#define HDIM 32
#define EDIM 32
#define D4 (4*DD)
#define DQKV 768

// ---------------- scratch (device globals; no runtime allocation) ----------
__device__ float    g_qkv[(size_t)NN*DQKV];    // q | k | v packed per row
__device__ float    g_ep[(size_t)NE*HDIM];
__device__ float    g_scores[(size_t)NE*HH];
__device__ unsigned g_smax[(size_t)NN*HH];
__device__ float    g_ssum[(size_t)NN*HH];
__device__ float    g_agg[(size_t)NN*DD];
__device__ float    g_x1 [(size_t)NN*DD];
__device__ float    g_bqkv[DQKV];
// bf16 hi/lo operand arrays
__device__ __nv_bfloat16 g_xnh[(size_t)NN*DD];
__device__ __nv_bfloat16 g_xnl[(size_t)NN*DD];
__device__ __nv_bfloat16 g_aggh[(size_t)NN*DD];
__device__ __nv_bfloat16 g_aggl[(size_t)NN*DD];
__device__ __nv_bfloat16 g_hh[(size_t)NN*D4];
__device__ __nv_bfloat16 g_hl[(size_t)NN*D4];
// weights packed (element offsets): Wq,Wk,Wv,Wo (65536 each), W1, W2 (262144)
#define WQO 0
#define WKO 65536
#define WVO 131072
#define WOO 196608
#define W1O 262144
#define W2O 524288
#define WTOT 786432
__device__ __nv_bfloat16 g_wh[WTOT];
__device__ __nv_bfloat16 g_wl[WTOT];

// ---------------- small helpers -------------------------------------------
__device__ __forceinline__ unsigned fenc(float f) {
    unsigned u = __float_as_uint(f);
    return (u & 0x80000000u) ? ~u : (u | 0x80000000u);
}
__device__ __forceinline__ float fdec(unsigned u) {
    return (u & 0x80000000u) ? __uint_as_float(u & 0x7fffffffu)
                             : __uint_as_float(~u);
}
__device__ __forceinline__ uint32_t pack_bf2(__nv_bfloat16 a, __nv_bfloat16 b) {
    return (uint32_t)__bfloat16_as_ushort(a) | ((uint32_t)__bfloat16_as_ushort(b) << 16);
}
__device__ __forceinline__ void cvt_hilo(float4 v, uint2& hi, uint2& lo) {
    __nv_bfloat16 hx = __float2bfloat16(v.x);
    __nv_bfloat16 hy = __float2bfloat16(v.y);
    __nv_bfloat16 hz = __float2bfloat16(v.z);
    __nv_bfloat16 hw = __float2bfloat16(v.w);
    __nv_bfloat16 lx = __float2bfloat16(v.x - __bfloat162float(hx));
    __nv_bfloat16 ly = __float2bfloat16(v.y - __bfloat162float(hy));
    __nv_bfloat16 lz = __float2bfloat16(v.z - __bfloat162float(hz));
    __nv_bfloat16 lw = __float2bfloat16(v.w - __bfloat162float(hw));
    hi.x = pack_bf2(hx, hy); hi.y = pack_bf2(hz, hw);
    lo.x = pack_bf2(lx, ly); lo.y = pack_bf2(lz, lw);
}
__device__ __forceinline__ float gelu_exact(float x) {
    return 0.5f * x * (1.0f + erff(x * 0.70710678118654752f));
}
__device__ __forceinline__ uint32_t smem_u32(const void* p) {
    uint32_t a;
    asm("{ .reg .u64 t; cvta.to.shared.u64 t, %1; cvt.u32.u64 %0, t; }"
        : "=r"(a) : "l"(p));
    return a;
}
__device__ __forceinline__ void cpa16(uint32_t dst, const void* src, bool p) {
    int sz = p ? 16 : 0;
    asm volatile("cp.async.cg.shared.global [%0], [%1], 16, %2;"
                 :: "r"(dst), "l"(src), "r"(sz));
}
__device__ __forceinline__ void red4(float* p, float a, float b, float c, float d) {
    asm volatile("red.global.add.v4.f32 [%0], {%1, %2, %3, %4};"
                 :: "l"(p), "f"(a), "f"(b), "f"(c), "f"(d) : "memory");
}

// ============== bf16 hi/lo GEMM: C = act(A[M,K] @ B[N,K]^T + bias) =========
// MODE 0: C fp32; MODE 1: C = res + scale*(val+bias); MODE 2: GELU -> bf16 hi/lo
#define LDT 40
#define TILE_B (128*LDT*2)          // 10240 B
#define STAGE_B (4*TILE_B)          // 40960 B (Ahi,Alo,Bhi,Blo)
#define GEMM_SMEM (2*STAGE_B)       // 81920 B (also covers 128x132 fp32 epilogue)

__device__ __forceinline__ void stage_load(
    char* smem, int buf,
    const __nv_bfloat16* __restrict__ Ahi, const __nv_bfloat16* __restrict__ Alo,
    const __nv_bfloat16* __restrict__ Bhi, const __nv_bfloat16* __restrict__ Blo,
    int bm, int bn, int M, int K, int kc, int tid)
{
    uint32_t sb = smem_u32(smem) + buf * STAGE_B;
    #pragma unroll
    for (int j = 0; j < 2; j++) {
        int idx = tid + j*256;               // 0..511 chunks of 16B
        int row = idx >> 2;                  // 0..127
        int c   = (idx & 3) * 8;             // bf16 column
        uint32_t soff = (uint32_t)(row*LDT + c) * 2;
        size_t gA = (size_t)(bm + row) * K + kc*32 + c;
        size_t gB = (size_t)(bn + row) * K + kc*32 + c;
        bool pa = (bm + row) < M;
        cpa16(sb + soff,              pa ? (const void*)(Ahi + gA) : (const void*)Ahi, pa);
        cpa16(sb + TILE_B + soff,     pa ? (const void*)(Alo + gA) : (const void*)Alo, pa);
        cpa16(sb + 2*TILE_B + soff,   Bhi + gB, true);
        cpa16(sb + 3*TILE_B + soff,   Blo + gB, true);
    }
    asm volatile("cp.async.commit_group;" ::: "memory");
}

template<int MODE>
__global__ void __launch_bounds__(256, 2)
tc_gemm(const __nv_bfloat16* __restrict__ Ahi, const __nv_bfloat16* __restrict__ Alo,
        const __nv_bfloat16* __restrict__ Bhi, const __nv_bfloat16* __restrict__ Blo,
        const float* __restrict__ bias, float* __restrict__ C,
        __nv_bfloat16* __restrict__ Chi, __nv_bfloat16* __restrict__ Clo,
        int M, int N, int K,
        const float* __restrict__ res, const float* __restrict__ scalep)
{
    extern __shared__ char smem[];
    const int tid = threadIdx.x;
    const int bm = blockIdx.y * 128;
    const int bn = blockIdx.x * 128;
    const int warp = tid >> 5;
    const int wm = (warp >> 2) * 64;
    const int wn = (warp & 3) * 32;

    wmma::fragment<wmma::accumulator, 16, 16, 16, float> fc[4][2];
    #pragma unroll
    for (int i = 0; i < 4; i++)
        #pragma unroll
        for (int j = 0; j < 2; j++)
            wmma::fill_fragment(fc[i][j], 0.0f);

    const int nch = K >> 5;
    stage_load(smem, 0, Ahi, Alo, Bhi, Blo, bm, bn, M, K, 0, tid);
    if (nch > 1) stage_load(smem, 1, Ahi, Alo, Bhi, Blo, bm, bn, M, K, 1, tid);

    for (int kc = 0; kc < nch; kc++) {
        if (kc + 1 < nch) asm volatile("cp.async.wait_group 1;" ::: "memory");
        else              asm volatile("cp.async.wait_group 0;" ::: "memory");
        __syncthreads();

        const char* base = smem + (kc & 1) * STAGE_B;
        const __nv_bfloat16* pAh = (const __nv_bfloat16*)(base);
        const __nv_bfloat16* pAl = (const __nv_bfloat16*)(base + TILE_B);
        const __nv_bfloat16* pBh = (const __nv_bfloat16*)(base + 2*TILE_B);
        const __nv_bfloat16* pBl = (const __nv_bfloat16*)(base + 3*TILE_B);

        #pragma unroll
        for (int ks = 0; ks < 32; ks += 16) {
            wmma::fragment<wmma::matrix_b, 16, 16, 16, __nv_bfloat16, wmma::col_major> fbh[2], fbl[2];
            #pragma unroll
            for (int j = 0; j < 2; j++) {
                wmma::load_matrix_sync(fbh[j], pBh + (wn + 16*j)*LDT + ks, LDT);
                wmma::load_matrix_sync(fbl[j], pBl + (wn + 16*j)*LDT + ks, LDT);
            }
            #pragma unroll
            for (int i = 0; i < 4; i++) {
                wmma::fragment<wmma::matrix_a, 16, 16, 16, __nv_bfloat16, wmma::row_major> fah, fal;
                wmma::load_matrix_sync(fah, pAh + (wm + 16*i)*LDT + ks, LDT);
                wmma::load_matrix_sync(fal, pAl + (wm + 16*i)*LDT + ks, LDT);
                #pragma unroll
                for (int j = 0; j < 2; j++) {
                    wmma::mma_sync(fc[i][j], fah, fbh[j], fc[i][j]);
                    wmma::mma_sync(fc[i][j], fah, fbl[j], fc[i][j]);
                    wmma::mma_sync(fc[i][j], fal, fbh[j], fc[i][j]);
                }
            }
        }
        __syncthreads();
        if (kc + 2 < nch)
            stage_load(smem, kc & 1, Ahi, Alo, Bhi, Blo, bm, bn, M, K, kc + 2, tid);
    }

    // ---- epilogue through SMEM ----
    float* Cs = (float*)smem;    // 128 x 132
    #pragma unroll
    for (int i = 0; i < 4; i++)
        #pragma unroll
        for (int j = 0; j < 2; j++)
            wmma::store_matrix_sync(Cs + (wm + 16*i)*132 + wn + 16*j, fc[i][j],
                                    132, wmma::mem_row_major);
    __syncthreads();

    const float scale = (MODE == 1) ? scalep[0] : 1.0f;
    int row = tid >> 1;
    int cbase = (tid & 1) * 64;
    int m = bm + row;
    if (m < M) {
        #pragma unroll
        for (int j = 0; j < 64; j += 4) {
            int n = bn + cbase + j;
            float4 v = *(float4*)(Cs + row*132 + cbase + j);
            float4 bi = *(const float4*)(bias + n);
            v.x += bi.x; v.y += bi.y; v.z += bi.z; v.w += bi.w;
            if (MODE == 2) {
                v.x = gelu_exact(v.x); v.y = gelu_exact(v.y);
                v.z = gelu_exact(v.z); v.w = gelu_exact(v.w);
                uint2 hi, lo;
                cvt_hilo(v, hi, lo);
                *(uint2*)(Chi + (size_t)m*N + n) = hi;
                *(uint2*)(Clo + (size_t)m*N + n) = lo;
            } else {
                if (MODE == 1) {
                    float4 r = *(const float4*)(res + (size_t)m*N + n);
                    v.x = r.x + scale*v.x; v.y = r.y + scale*v.y;
                    v.z = r.z + scale*v.z; v.w = r.w + scale*v.w;
                }
                *(float4*)(C + (size_t)m*N + n) = v;
            }
        }
    }
}

// ---------------- all weights + qkv bias -> bf16 hi/lo (one launch) --------
__global__ void cvt_all(const float* __restrict__ Wq, const float* __restrict__ Wk,
                        const float* __restrict__ Wv, const float* __restrict__ Wo,
                        const float* __restrict__ W1, const float* __restrict__ W2,
                        const float* __restrict__ bq, const float* __restrict__ bk,
                        const float* __restrict__ bv) {
    int i = blockIdx.x * blockDim.x + threadIdx.x;   // float4 index, 196608 total
    if (i < WTOT/4) {
        const float* src; int off;
        if      (i < 16384)  { src = Wq; off = 0; }
        else if (i < 32768)  { src = Wk; off = 16384; }
        else if (i < 49152)  { src = Wv; off = 32768; }
        else if (i < 65536)  { src = Wo; off = 49152; }
        else if (i < 131072) { src = W1; off = 65536; }
        else                 { src = W2; off = 131072; }
        float4 v = ((const float4*)src)[i - off];
        uint2 h, l;
        cvt_hilo(v, h, l);
        ((uint2*)g_wh)[i] = h;
        ((uint2*)g_wl)[i] = l;
    }
    if (i < DQKV/4) {
        const float* bs = (i < 64) ? bq : ((i < 128) ? bk : bv);
        ((float4*)g_bqkv)[i] = ((const float4*)bs)[i & 63];
    }
}

// ---------------- zero init (agg, ssum, smax) ------------------------------
__global__ void zero_kernel() {
    int i = blockIdx.x * blockDim.x + threadIdx.x;
    if (i < NN*DD) g_agg[i] = 0.f;
    if (i < NN*HH) { g_ssum[i] = 0.f; g_smax[i] = 0u; }
}

// ---------------- layernorm -> bf16 hi/lo ----------------------------------
__global__ void ln_kernel(const float* __restrict__ in,
                          const float* __restrict__ g,
                          const float* __restrict__ b,
                          __nv_bfloat16* __restrict__ out_hi,
                          __nv_bfloat16* __restrict__ out_lo) {
    int row = blockIdx.x;
    int t = threadIdx.x;
    float v = in[(size_t)row*DD + t];
    float s = v, s2 = v*v;
    #pragma unroll
    for (int off = 16; off; off >>= 1) {
        s  += __shfl_xor_sync(0xffffffffu, s,  off);
        s2 += __shfl_xor_sync(0xffffffffu, s2, off);
    }
    __shared__ float ws[8], ws2[8], mustd[2];
    int w = t >> 5, lane = t & 31;
    if (lane == 0) { ws[w] = s; ws2[w] = s2; }
    __syncthreads();
    if (t == 0) {
        float ts = 0.f, ts2 = 0.f;
        #pragma unroll
        for (int i = 0; i < 8; i++) { ts += ws[i]; ts2 += ws2[i]; }
        float mu = ts * (1.0f/DD);
        float var = ts2 * (1.0f/DD) - mu*mu;
        mustd[0] = mu;
        mustd[1] = 1.0f / sqrtf(var + 1e-5f);
    }
    __syncthreads();
    float y = (v - mustd[0]) * mustd[1] * g[t] + b[t];
    __nv_bfloat16 h = __float2bfloat16(y);
    out_hi[(size_t)row*DD + t] = h;
    out_lo[(size_t)row*DD + t] = __float2bfloat16(y - __bfloat162float(h));
}

// ---------------- edge projection: ep[E,32] = ef[E,32] @ We[32,32]^T + be --
__global__ __launch_bounds__(256)
void ep_kernel(const float* __restrict__ ef, const float* __restrict__ We,
               const float* __restrict__ be) {
    __shared__ float WeT[EDIM][HDIM+1];
    __shared__ float bsh[HDIM];
    int tid = threadIdx.x;
    for (int i = tid; i < HDIM*EDIM; i += 256) {
        int r = i / EDIM, c = i % EDIM;
        WeT[c][r] = We[i];
    }
    if (tid < HDIM) bsh[tid] = be[tid];
    __syncthreads();
    int warp = tid >> 5, lane = tid & 31;
    size_t e = (size_t)blockIdx.x * 8 + warp;
    if (e >= NE) return;
    float f = ef[e*EDIM + lane];
    float acc = bsh[lane];
    #pragma unroll
    for (int k2 = 0; k2 < EDIM; k2++) {
        float fk = __shfl_sync(0xffffffffu, f, k2);
        acc = fmaf(fk, WeT[k2][lane], acc);
    }
    g_ep[e*HDIM + lane] = acc;
}

// ---------------- per-edge scores + segment max ----------------------------
__global__ __launch_bounds__(256)
void scores_kernel(const int* __restrict__ ei, const float* __restrict__ ew) {
    int lane = threadIdx.x & 31;
    size_t e = (size_t)blockIdx.x * 8 + (threadIdx.x >> 5);
    if (e >= NE) return;
    int src = ei[e];
    int dst = ei[NE + e];
    float epv = g_ep[e*HDIM + lane];
    const float* qr = g_qkv + (size_t)dst*DQKV + lane;          // q
    const float* kr = g_qkv + (size_t)src*DQKV + DD + lane;     // k
    float acc[HH];
    #pragma unroll
    for (int h = 0; h < HH; h++)
        acc[h] = qr[h*HDIM] * (kr[h*HDIM] + epv);
    #pragma unroll
    for (int off = 16; off; off >>= 1)
        #pragma unroll
        for (int h = 0; h < HH; h++)
            acc[h] += __shfl_xor_sync(0xffffffffu, acc[h], off);
    if (lane == 0) {
        float w = ew[e] * 0.17677669529663687f;
        #pragma unroll
        for (int h = 0; h < HH; h++) {
            float s = acc[h] * w;
            g_scores[e*HH + h] = s;
            atomicMax(&g_smax[dst*HH + h], fenc(s));
        }
    }
}

// ------- fused: exp(score-max), red ssum, scatter unnormalized e*v ---------
__global__ __launch_bounds__(256)
void expagg_kernel(const int* __restrict__ ei) {
    int lane = threadIdx.x & 31;
    size_t e = (size_t)blockIdx.x * 8 + (threadIdx.x >> 5);
    if (e >= NE) return;
    int src = ei[e];
    int dst = ei[NE + e];
    float ev = 0.f;
    if (lane < HH) {
        float m = fdec(g_smax[(size_t)dst*HH + lane]);
        ev = expf(g_scores[e*HH + lane] - m);
        g_scores[e*HH + lane] = ev;          // keep e for attn-weights pass
    }
    float wh[HH];
    #pragma unroll
    for (int h = 0; h < HH; h++)
        wh[h] = __shfl_sync(0xffffffffu, ev, h);
    float* sp = g_ssum + (size_t)dst*HH;
    if (lane == 0) red4(sp,     wh[0], wh[1], wh[2], wh[3]);
    if (lane == 1) red4(sp + 4, wh[4], wh[5], wh[6], wh[7]);
    float w0 = wh[lane >> 3];
    float w1 = wh[4 + (lane >> 3)];
    const float4* vr = (const float4*)(g_qkv + (size_t)src*DQKV + 2*DD);  // v
    float* ar = g_agg + (size_t)dst*DD;
    float4 v0 = vr[lane];
    float4 v1 = vr[lane + 32];
    red4(ar + 4*lane,       w0*v0.x, w0*v0.y, w0*v0.z, w0*v0.w);
    red4(ar + 128 + 4*lane, w1*v1.x, w1*v1.y, w1*v1.z, w1*v1.w);
}

// ---------------- attn weights output: e / ssum[dst] -----------------------
__global__ void attnw_kernel(const int* __restrict__ ei, float* __restrict__ attn_out) {
    int e = blockIdx.x * blockDim.x + threadIdx.x;
    if (e >= NE) return;
    int dst = ei[NE + e];
    float4 e0 = *(float4*)(g_scores + (size_t)e*HH);
    float4 e1 = *(float4*)(g_scores + (size_t)e*HH + 4);
    float4 s0 = *(const float4*)(g_ssum + (size_t)dst*HH);
    float4 s1 = *(const float4*)(g_ssum + (size_t)dst*HH + 4);
    e0.x /= s0.x; e0.y /= s0.y; e0.z /= s0.z; e0.w /= s0.w;
    e1.x /= s1.x; e1.y /= s1.y; e1.z /= s1.z; e1.w /= s1.w;
    *(float4*)(attn_out + (size_t)e*HH)     = e0;
    *(float4*)(attn_out + (size_t)e*HH + 4) = e1;
}

// -------- normalize agg by ssum and convert -> bf16 hi/lo ------------------
__global__ void cvt_agg_norm(int n4) {
    int i = blockIdx.x * blockDim.x + threadIdx.x;
    if (i >= n4) return;
    int node = i >> 6;             // 64 float4 per 256-float row
    int j = i & 63;
    int head = j >> 3;
    float s = 1.0f / g_ssum[(size_t)node*HH + head];
    float4 v = ((const float4*)g_agg)[i];
    v.x *= s; v.y *= s; v.z *= s; v.w *= s;
    uint2 h, l;
    cvt_hilo(v, h, l);
    ((uint2*)g_aggh)[i] = h;
    ((uint2*)g_aggl)[i] = l;
}

// ---------------------------------------------------------------------------
extern "C" void kernel_launch(void* const* d_in, const int* in_sizes, int n_in,
                              void* d_out, int out_size) {
    const float* x     = (const float*)d_in[0];
    const int*   ei    = (const int*)  d_in[1];
    const float* ef    = (const float*)d_in[2];
    const float* ew    = (const float*)d_in[3];
    const float* Wq    = (const float*)d_in[4];
    const float* bq    = (const float*)d_in[5];
    const float* Wk    = (const float*)d_in[6];
    const float* bk    = (const float*)d_in[7];
    const float* Wv    = (const float*)d_in[8];
    const float* bv    = (const float*)d_in[9];
    const float* We    = (const float*)d_in[10];
    const float* be    = (const float*)d_in[11];
    const float* Wo    = (const float*)d_in[12];
    const float* bo    = (const float*)d_in[13];
    const float* W1    = (const float*)d_in[14];
    const float* b1    = (const float*)d_in[15];
    const float* W2    = (const float*)d_in[16];
    const float* b2    = (const float*)d_in[17];
    const float* g1    = (const float*)d_in[18];
    const float* be1   = (const float*)d_in[19];
    const float* g2    = (const float*)d_in[20];
    const float* be2   = (const float*)d_in[21];
    const float* alpha = (const float*)d_in[22];
    const float* beta  = (const float*)d_in[23];

    float* out = (float*)d_out;
    float* out_x = out;
    float* out_attn = nullptr;
    if (out_size >= NN*DD + NE*HH) out_attn = out + (size_t)NN*DD;

    float *p_qkv, *p_agg, *p_x1, *p_bqkv;
    __nv_bfloat16 *p_xnh, *p_xnl, *p_aggh, *p_aggl, *p_hh, *p_hl, *p_wh, *p_wl;
    cudaGetSymbolAddress((void**)&p_qkv,  g_qkv);
    cudaGetSymbolAddress((void**)&p_agg,  g_agg);
    cudaGetSymbolAddress((void**)&p_x1,   g_x1);
    cudaGetSymbolAddress((void**)&p_bqkv, g_bqkv);
    cudaGetSymbolAddress((void**)&p_xnh,  g_xnh);
    cudaGetSymbolAddress((void**)&p_xnl,  g_xnl);
    cudaGetSymbolAddress((void**)&p_aggh, g_aggh);
    cudaGetSymbolAddress((void**)&p_aggl, g_aggl);
    cudaGetSymbolAddress((void**)&p_hh,   g_hh);
    cudaGetSymbolAddress((void**)&p_hl,   g_hl);
    cudaGetSymbolAddress((void**)&p_wh,   g_wh);
    cudaGetSymbolAddress((void**)&p_wl,   g_wl);

    cudaFuncSetAttribute(tc_gemm<0>, cudaFuncAttributeMaxDynamicSharedMemorySize, GEMM_SMEM);
    cudaFuncSetAttribute(tc_gemm<1>, cudaFuncAttributeMaxDynamicSharedMemorySize, GEMM_SMEM);
    cudaFuncSetAttribute(tc_gemm<2>, cudaFuncAttributeMaxDynamicSharedMemorySize, GEMM_SMEM);

    const int eblocks = (NE + 7) / 8;
    const int mtiles = (NN + 127) / 128;   // 391

    // 1. zero accumulators
    zero_kernel<<<(NN*DD + 255) / 256, 256>>>();

    // 2. all weight/bias conversions in one launch
    cvt_all<<<(WTOT/4 + 255) / 256, 256>>>(Wq, Wk, Wv, Wo, W1, W2, bq, bk, bv);

    // 3. LN1 -> bf16 hi/lo
    ln_kernel<<<NN, 256>>>(x, g1, be1, p_xnh, p_xnl);

    // 4. edge projection
    ep_kernel<<<eblocks, 256>>>(ef, We, be);

    // 5. fused qkv projection (launch #5 -> ncu profile target)
    dim3 gqkv(DQKV/128, mtiles);
    tc_gemm<0><<<gqkv, 256, GEMM_SMEM>>>(p_xnh, p_xnl, p_wh + WQO, p_wl + WQO,
                                         p_bqkv, p_qkv, nullptr, nullptr,
                                         NN, DQKV, DD, nullptr, nullptr);

    // 6. scores + segment max
    scores_kernel<<<eblocks, 256>>>(ei, ew);

    // 7. fused exp + ssum + unnormalized scatter-aggregate
    expagg_kernel<<<eblocks, 256>>>(ei);

    // 8. attn weights output
    if (out_attn)
        attnw_kernel<<<(NE + 255) / 256, 256>>>(ei, out_attn);

    // 9. normalize agg + convert to bf16 hi/lo
    cvt_agg_norm<<<(NN*DD/4 + 255) / 256, 256>>>(NN*DD/4);

    // 10. attn out projection + residual
    dim3 g256(DD/128, mtiles);
    tc_gemm<1><<<g256, 256, GEMM_SMEM>>>(p_aggh, p_aggl, p_wh + WOO, p_wl + WOO,
                                         bo, p_x1, nullptr, nullptr, NN, DD, DD, x, alpha);

    // 11. LN2 -> bf16 hi/lo
    ln_kernel<<<NN, 256>>>(p_x1, g2, be2, p_xnh, p_xnl);

    // 12. FFN up + GELU -> bf16 hi/lo h
    dim3 g1024(D4/128, mtiles);
    tc_gemm<2><<<g1024, 256, GEMM_SMEM>>>(p_xnh, p_xnl, p_wh + W1O, p_wl + W1O,
                                          b1, nullptr, p_hh, p_hl, NN, D4, DD, nullptr, nullptr);

    // 13. FFN down + residual -> final x into d_out
    tc_gemm<1><<<g256, 256, GEMM_SMEM>>>(p_hh, p_hl, p_wh + W2O, p_wl + W2O,
                                         b2, out_x, nullptr, nullptr, NN, DD, D4, p_x1, beta);
}

// round 13
// speedup vs baseline: 1.8619x; 1.2331x over previous
#include <cuda_runtime.h>
#include <cuda_bf16.h>
#include <mma.h>
#include <math.h>
#include <stdint.h>

using namespace nvcuda;

#define NN 50000
#define NE 1600000
#define DD 256
#define HH 8
#define HDIM 32
#define EDIM 32
#define D4 (4*DD)
#define DQKV 768

// ---------------- scratch (device globals; no runtime allocation) ----------
__device__ float    g_qkv[(size_t)NN*DQKV];    // q | k | v packed per row
__device__ float    g_ep[(size_t)NE*HDIM];
__device__ float    g_scores[(size_t)NE*HH];
__device__ unsigned g_smax[(size_t)NN*HH];
__device__ float    g_ssum[(size_t)NN*HH];
__device__ float    g_agg[(size_t)NN*DD];
__device__ float    g_x1 [(size_t)NN*DD];
__device__ float    g_bqkv[DQKV];
// bf16 hi/lo operand arrays
__device__ __nv_bfloat16 g_xnh[(size_t)NN*DD];
__device__ __nv_bfloat16 g_xnl[(size_t)NN*DD];
__device__ __nv_bfloat16 g_aggh[(size_t)NN*DD];
__device__ __nv_bfloat16 g_aggl[(size_t)NN*DD];
__device__ __nv_bfloat16 g_hh[(size_t)NN*D4];
__device__ __nv_bfloat16 g_hl[(size_t)NN*D4];
// weights packed (element offsets): Wq,Wk,Wv,Wo (65536 each), W1, W2 (262144)
#define WQO 0
#define WKO 65536
#define WVO 131072
#define WOO 196608
#define W1O 262144
#define W2O 524288
#define WTOT 786432
__device__ __nv_bfloat16 g_wh[WTOT];
__device__ __nv_bfloat16 g_wl[WTOT];

// ---------------- small helpers -------------------------------------------
__device__ __forceinline__ unsigned fenc(float f) {
    unsigned u = __float_as_uint(f);
    return (u & 0x80000000u) ? ~u : (u | 0x80000000u);
}
__device__ __forceinline__ float fdec(unsigned u) {
    return (u & 0x80000000u) ? __uint_as_float(u & 0x7fffffffu)
                             : __uint_as_float(~u);
}
__device__ __forceinline__ uint32_t pack_bf2(__nv_bfloat16 a, __nv_bfloat16 b) {
    return (uint32_t)__bfloat16_as_ushort(a) | ((uint32_t)__bfloat16_as_ushort(b) << 16);
}
__device__ __forceinline__ void cvt_hilo(float4 v, uint2& hi, uint2& lo) {
    __nv_bfloat16 hx = __float2bfloat16(v.x);
    __nv_bfloat16 hy = __float2bfloat16(v.y);
    __nv_bfloat16 hz = __float2bfloat16(v.z);
    __nv_bfloat16 hw = __float2bfloat16(v.w);
    __nv_bfloat16 lx = __float2bfloat16(v.x - __bfloat162float(hx));
    __nv_bfloat16 ly = __float2bfloat16(v.y - __bfloat162float(hy));
    __nv_bfloat16 lz = __float2bfloat16(v.z - __bfloat162float(hz));
    __nv_bfloat16 lw = __float2bfloat16(v.w - __bfloat162float(hw));
    hi.x = pack_bf2(hx, hy); hi.y = pack_bf2(hz, hw);
    lo.x = pack_bf2(lx, ly); lo.y = pack_bf2(lz, lw);
}
__device__ __forceinline__ float gelu_exact(float x) {
    return 0.5f * x * (1.0f + erff(x * 0.70710678118654752f));
}
__device__ __forceinline__ uint32_t smem_u32(const void* p) {
    uint32_t a;
    asm("{ .reg .u64 t; cvta.to.shared.u64 t, %1; cvt.u32.u64 %0, t; }"
        : "=r"(a) : "l"(p));
    return a;
}
__device__ __forceinline__ void cpa16(uint32_t dst, const void* src, bool p) {
    int sz = p ? 16 : 0;
    asm volatile("cp.async.cg.shared.global [%0], [%1], 16, %2;"
                 :: "r"(dst), "l"(src), "r"(sz));
}
__device__ __forceinline__ void red4(float* p, float a, float b, float c, float d) {
    asm volatile("red.global.add.v4.f32 [%0], {%1, %2, %3, %4};"
                 :: "l"(p), "f"(a), "f"(b), "f"(c), "f"(d) : "memory");
}
__device__ __forceinline__ void red1(float* p, float a) {
    asm volatile("red.global.add.f32 [%0], %1;" :: "l"(p), "f"(a) : "memory");
}

// ============== bf16 hi/lo GEMM: C = act(A[M,K] @ B[N,K]^T + bias) =========
// MODE 0: C fp32; MODE 1: C = res + scale*(val+bias); MODE 2: GELU -> bf16 hi/lo
#define LDT 40
#define TILE_B (128*LDT*2)          // 10240 B
#define STAGE_B (4*TILE_B)          // 40960 B (Ahi,Alo,Bhi,Blo)
#define GEMM_SMEM (2*STAGE_B)       // 81920 B (also covers 128x132 fp32 epilogue)

__device__ __forceinline__ void stage_load(
    char* smem, int buf,
    const __nv_bfloat16* __restrict__ Ahi, const __nv_bfloat16* __restrict__ Alo,
    const __nv_bfloat16* __restrict__ Bhi, const __nv_bfloat16* __restrict__ Blo,
    int bm, int bn, int M, int K, int kc, int tid)
{
    uint32_t sb = smem_u32(smem) + buf * STAGE_B;
    #pragma unroll
    for (int j = 0; j < 2; j++) {
        int idx = tid + j*256;               // 0..511 chunks of 16B
        int row = idx >> 2;                  // 0..127
        int c   = (idx & 3) * 8;             // bf16 column
        uint32_t soff = (uint32_t)(row*LDT + c) * 2;
        size_t gA = (size_t)(bm + row) * K + kc*32 + c;
        size_t gB = (size_t)(bn + row) * K + kc*32 + c;
        bool pa = (bm + row) < M;
        cpa16(sb + soff,              pa ? (const void*)(Ahi + gA) : (const void*)Ahi, pa);
        cpa16(sb + TILE_B + soff,     pa ? (const void*)(Alo + gA) : (const void*)Alo, pa);
        cpa16(sb + 2*TILE_B + soff,   Bhi + gB, true);
        cpa16(sb + 3*TILE_B + soff,   Blo + gB, true);
    }
    asm volatile("cp.async.commit_group;" ::: "memory");
}

template<int MODE>
__global__ void __launch_bounds__(256, 2)
tc_gemm(const __nv_bfloat16* __restrict__ Ahi, const __nv_bfloat16* __restrict__ Alo,
        const __nv_bfloat16* __restrict__ Bhi, const __nv_bfloat16* __restrict__ Blo,
        const float* __restrict__ bias, float* __restrict__ C,
        __nv_bfloat16* __restrict__ Chi, __nv_bfloat16* __restrict__ Clo,
        int M, int N, int K,
        const float* __restrict__ res, const float* __restrict__ scalep)
{
    extern __shared__ char smem[];
    const int tid = threadIdx.x;
    const int bm = blockIdx.y * 128;
    const int bn = blockIdx.x * 128;
    const int warp = tid >> 5;
    const int wm = (warp >> 2) * 64;
    const int wn = (warp & 3) * 32;

    wmma::fragment<wmma::accumulator, 16, 16, 16, float> fc[4][2];
    #pragma unroll
    for (int i = 0; i < 4; i++)
        #pragma unroll
        for (int j = 0; j < 2; j++)
            wmma::fill_fragment(fc[i][j], 0.0f);

    const int nch = K >> 5;
    stage_load(smem, 0, Ahi, Alo, Bhi, Blo, bm, bn, M, K, 0, tid);
    if (nch > 1) stage_load(smem, 1, Ahi, Alo, Bhi, Blo, bm, bn, M, K, 1, tid);

    for (int kc = 0; kc < nch; kc++) {
        if (kc + 1 < nch) asm volatile("cp.async.wait_group 1;" ::: "memory");
        else              asm volatile("cp.async.wait_group 0;" ::: "memory");
        __syncthreads();

        const char* base = smem + (kc & 1) * STAGE_B;
        const __nv_bfloat16* pAh = (const __nv_bfloat16*)(base);
        const __nv_bfloat16* pAl = (const __nv_bfloat16*)(base + TILE_B);
        const __nv_bfloat16* pBh = (const __nv_bfloat16*)(base + 2*TILE_B);
        const __nv_bfloat16* pBl = (const __nv_bfloat16*)(base + 3*TILE_B);

        #pragma unroll
        for (int ks = 0; ks < 32; ks += 16) {
            wmma::fragment<wmma::matrix_b, 16, 16, 16, __nv_bfloat16, wmma::col_major> fbh[2], fbl[2];
            #pragma unroll
            for (int j = 0; j < 2; j++) {
                wmma::load_matrix_sync(fbh[j], pBh + (wn + 16*j)*LDT + ks, LDT);
                wmma::load_matrix_sync(fbl[j], pBl + (wn + 16*j)*LDT + ks, LDT);
            }
            #pragma unroll
            for (int i = 0; i < 4; i++) {
                wmma::fragment<wmma::matrix_a, 16, 16, 16, __nv_bfloat16, wmma::row_major> fah, fal;
                wmma::load_matrix_sync(fah, pAh + (wm + 16*i)*LDT + ks, LDT);
                wmma::load_matrix_sync(fal, pAl + (wm + 16*i)*LDT + ks, LDT);
                #pragma unroll
                for (int j = 0; j < 2; j++) {
                    wmma::mma_sync(fc[i][j], fah, fbh[j], fc[i][j]);
                    wmma::mma_sync(fc[i][j], fah, fbl[j], fc[i][j]);
                    wmma::mma_sync(fc[i][j], fal, fbh[j], fc[i][j]);
                }
            }
        }
        __syncthreads();
        if (kc + 2 < nch)
            stage_load(smem, kc & 1, Ahi, Alo, Bhi, Blo, bm, bn, M, K, kc + 2, tid);
    }

    // ---- epilogue through SMEM ----
    float* Cs = (float*)smem;    // 128 x 132
    #pragma unroll
    for (int i = 0; i < 4; i++)
        #pragma unroll
        for (int j = 0; j < 2; j++)
            wmma::store_matrix_sync(Cs + (wm + 16*i)*132 + wn + 16*j, fc[i][j],
                                    132, wmma::mem_row_major);
    __syncthreads();

    const float scale = (MODE == 1) ? scalep[0] : 1.0f;
    int row = tid >> 1;
    int cbase = (tid & 1) * 64;
    int m = bm + row;
    if (m < M) {
        #pragma unroll
        for (int j = 0; j < 64; j += 4) {
            int n = bn + cbase + j;
            float4 v = *(float4*)(Cs + row*132 + cbase + j);
            float4 bi = *(const float4*)(bias + n);
            v.x += bi.x; v.y += bi.y; v.z += bi.z; v.w += bi.w;
            if (MODE == 2) {
                v.x = gelu_exact(v.x); v.y = gelu_exact(v.y);
                v.z = gelu_exact(v.z); v.w = gelu_exact(v.w);
                uint2 hi, lo;
                cvt_hilo(v, hi, lo);
                *(uint2*)(Chi + (size_t)m*N + n) = hi;
                *(uint2*)(Clo + (size_t)m*N + n) = lo;
            } else {
                if (MODE == 1) {
                    float4 r = *(const float4*)(res + (size_t)m*N + n);
                    v.x = r.x + scale*v.x; v.y = r.y + scale*v.y;
                    v.z = r.z + scale*v.z; v.w = r.w + scale*v.w;
                }
                *(float4*)(C + (size_t)m*N + n) = v;
            }
        }
    }
}

// ---------------- all weights + qkv bias -> bf16 hi/lo (one launch) --------
__global__ void cvt_all(const float* __restrict__ Wq, const float* __restrict__ Wk,
                        const float* __restrict__ Wv, const float* __restrict__ Wo,
                        const float* __restrict__ W1, const float* __restrict__ W2,
                        const float* __restrict__ bq, const float* __restrict__ bk,
                        const float* __restrict__ bv) {
    int i = blockIdx.x * blockDim.x + threadIdx.x;   // float4 index, 196608 total
    if (i < WTOT/4) {
        const float* src; int off;
        if      (i < 16384)  { src = Wq; off = 0; }
        else if (i < 32768)  { src = Wk; off = 16384; }
        else if (i < 49152)  { src = Wv; off = 32768; }
        else if (i < 65536)  { src = Wo; off = 49152; }
        else if (i < 131072) { src = W1; off = 65536; }
        else                 { src = W2; off = 131072; }
        float4 v = ((const float4*)src)[i - off];
        uint2 h, l;
        cvt_hilo(v, h, l);
        ((uint2*)g_wh)[i] = h;
        ((uint2*)g_wl)[i] = l;
    }
    if (i < DQKV/4) {
        const float* bs = (i < 64) ? bq : ((i < 128) ? bk : bv);
        ((float4*)g_bqkv)[i] = ((const float4*)bs)[i & 63];
    }
}

// ---------------- zero init (agg, ssum, smax) ------------------------------
__global__ void zero_kernel() {
    int i = blockIdx.x * blockDim.x + threadIdx.x;
    if (i < NN*DD) g_agg[i] = 0.f;
    if (i < NN*HH) { g_ssum[i] = 0.f; g_smax[i] = 0u; }
}

// ---------------- layernorm -> bf16 hi/lo ----------------------------------
__global__ void ln_kernel(const float* __restrict__ in,
                          const float* __restrict__ g,
                          const float* __restrict__ b,
                          __nv_bfloat16* __restrict__ out_hi,
                          __nv_bfloat16* __restrict__ out_lo) {
    int row = blockIdx.x;
    int t = threadIdx.x;
    float v = in[(size_t)row*DD + t];
    float s = v, s2 = v*v;
    #pragma unroll
    for (int off = 16; off; off >>= 1) {
        s  += __shfl_xor_sync(0xffffffffu, s,  off);
        s2 += __shfl_xor_sync(0xffffffffu, s2, off);
    }
    __shared__ float ws[8], ws2[8], mustd[2];
    int w = t >> 5, lane = t & 31;
    if (lane == 0) { ws[w] = s; ws2[w] = s2; }
    __syncthreads();
    if (t == 0) {
        float ts = 0.f, ts2 = 0.f;
        #pragma unroll
        for (int i = 0; i < 8; i++) { ts += ws[i]; ts2 += ws2[i]; }
        float mu = ts * (1.0f/DD);
        float var = ts2 * (1.0f/DD) - mu*mu;
        mustd[0] = mu;
        mustd[1] = 1.0f / sqrtf(var + 1e-5f);
    }
    __syncthreads();
    float y = (v - mustd[0]) * mustd[1] * g[t] + b[t];
    __nv_bfloat16 h = __float2bfloat16(y);
    out_hi[(size_t)row*DD + t] = h;
    out_lo[(size_t)row*DD + t] = __float2bfloat16(y - __bfloat162float(h));
}

// -------- edge projection: thread-per-edge, zero shuffles ------------------
// ep[e][:] = ef[e][:] @ We^T + be ; We staged transposed in SMEM (broadcast reads)
__global__ __launch_bounds__(256)
void ep_kernel(const float* __restrict__ ef, const float* __restrict__ We,
               const float* __restrict__ be) {
    __shared__ float Wt[EDIM][HDIM];   // Wt[k][j] = We[j][k]
    __shared__ float bs[HDIM];
    int tid = threadIdx.x;
    #pragma unroll
    for (int i = tid; i < HDIM*EDIM; i += 256) {
        int r = i >> 5, c = i & 31;     // We[r][c]
        Wt[c][r] = We[i];
    }
    if (tid < HDIM) bs[tid] = be[tid];
    __syncthreads();
    size_t e = (size_t)blockIdx.x * 256 + tid;
    if (e >= NE) return;
    float4 f[8];
    const float4* efr = (const float4*)(ef + e*EDIM);
    #pragma unroll
    for (int i = 0; i < 8; i++) f[i] = efr[i];
    float4 acc[8];
    #pragma unroll
    for (int j = 0; j < 8; j++) acc[j] = ((const float4*)bs)[j];
    #pragma unroll
    for (int i = 0; i < 8; i++) {
        float fv[4] = {f[i].x, f[i].y, f[i].z, f[i].w};
        #pragma unroll
        for (int t2 = 0; t2 < 4; t2++) {
            float fk = fv[t2];
            const float4* wr = (const float4*)Wt[i*4 + t2];
            #pragma unroll
            for (int j = 0; j < 8; j++) {
                float4 w = wr[j];
                acc[j].x = fmaf(fk, w.x, acc[j].x);
                acc[j].y = fmaf(fk, w.y, acc[j].y);
                acc[j].z = fmaf(fk, w.z, acc[j].z);
                acc[j].w = fmaf(fk, w.w, acc[j].w);
            }
        }
    }
    float4* out = (float4*)(g_ep + e*HDIM);
    #pragma unroll
    for (int j = 0; j < 8; j++) out[j] = acc[j];
}

// -------- per-edge scores + segment max: 4 lanes per head, 2 shuffles ------
__global__ __launch_bounds__(256)
void scores_kernel(const int* __restrict__ ei, const float* __restrict__ ew) {
    int lane = threadIdx.x & 31;
    size_t e = (size_t)blockIdx.x * 8 + (threadIdx.x >> 5);
    if (e >= NE) return;
    int src = ei[e];
    int dst = ei[NE + e];
    int h = lane >> 2, s = lane & 3;
    const float4* q4 = (const float4*)(g_qkv + (size_t)dst*DQKV);
    const float4* k4 = (const float4*)(g_qkv + (size_t)src*DQKV + DD);
    const float4* e4 = (const float4*)(g_ep + e*HDIM);
    int qi = h*8 + s*2;
    float4 qa = q4[qi],   qb = q4[qi+1];
    float4 ka = k4[qi],   kb = k4[qi+1];
    float4 ea = e4[s*2],  eb = e4[s*2+1];
    float p = qa.x*(ka.x+ea.x) + qa.y*(ka.y+ea.y) + qa.z*(ka.z+ea.z) + qa.w*(ka.w+ea.w)
            + qb.x*(kb.x+eb.x) + qb.y*(kb.y+eb.y) + qb.z*(kb.z+eb.z) + qb.w*(kb.w+eb.w);
    p += __shfl_xor_sync(0xffffffffu, p, 1);
    p += __shfl_xor_sync(0xffffffffu, p, 2);
    if (s == 0) {
        float w = ew[e] * 0.17677669529663687f;
        float sc = p * w;
        g_scores[e*HH + h] = sc;
        atomicMax(&g_smax[(size_t)dst*HH + h], fenc(sc));
    }
}

// ------- fused: exp(score-max), red ssum, scatter unnormalized e*v ---------
__global__ __launch_bounds__(256)
void expagg_kernel(const int* __restrict__ ei) {
    int lane = threadIdx.x & 31;
    size_t e = (size_t)blockIdx.x * 8 + (threadIdx.x >> 5);
    if (e >= NE) return;
    int src = ei[e];
    int dst = ei[NE + e];
    float ev = 0.f;
    if (lane < HH) {
        float m = fdec(g_smax[(size_t)dst*HH + lane]);
        ev = expf(g_scores[e*HH + lane] - m);
        g_scores[e*HH + lane] = ev;          // keep e for attn-weights pass
        red1(g_ssum + (size_t)dst*HH + lane, ev);
    }
    float w0 = __shfl_sync(0xffffffffu, ev, lane >> 3);
    float w1 = __shfl_sync(0xffffffffu, ev, 4 + (lane >> 3));
    const float4* vr = (const float4*)(g_qkv + (size_t)src*DQKV + 2*DD);  // v
    float* ar = g_agg + (size_t)dst*DD;
    float4 v0 = vr[lane];
    float4 v1 = vr[lane + 32];
    red4(ar + 4*lane,       w0*v0.x, w0*v0.y, w0*v0.z, w0*v0.w);
    red4(ar + 128 + 4*lane, w1*v1.x, w1*v1.y, w1*v1.z, w1*v1.w);
}

// ---------------- attn weights output: e / ssum[dst] -----------------------
__global__ void attnw_kernel(const int* __restrict__ ei, float* __restrict__ attn_out) {
    int e = blockIdx.x * blockDim.x + threadIdx.x;
    if (e >= NE) return;
    int dst = ei[NE + e];
    float4 e0 = *(float4*)(g_scores + (size_t)e*HH);
    float4 e1 = *(float4*)(g_scores + (size_t)e*HH + 4);
    float4 s0 = *(const float4*)(g_ssum + (size_t)dst*HH);
    float4 s1 = *(const float4*)(g_ssum + (size_t)dst*HH + 4);
    e0.x /= s0.x; e0.y /= s0.y; e0.z /= s0.z; e0.w /= s0.w;
    e1.x /= s1.x; e1.y /= s1.y; e1.z /= s1.z; e1.w /= s1.w;
    *(float4*)(attn_out + (size_t)e*HH)     = e0;
    *(float4*)(attn_out + (size_t)e*HH + 4) = e1;
}

// -------- normalize agg by ssum and convert -> bf16 hi/lo ------------------
__global__ void cvt_agg_norm(int n4) {
    int i = blockIdx.x * blockDim.x + threadIdx.x;
    if (i >= n4) return;
    int node = i >> 6;             // 64 float4 per 256-float row
    int j = i & 63;
    int head = j >> 3;
    float s = 1.0f / g_ssum[(size_t)node*HH + head];
    float4 v = ((const float4*)g_agg)[i];
    v.x *= s; v.y *= s; v.z *= s; v.w *= s;
    uint2 h, l;
    cvt_hilo(v, h, l);
    ((uint2*)g_aggh)[i] = h;
    ((uint2*)g_aggl)[i] = l;
}

// ---------------------------------------------------------------------------
extern "C" void kernel_launch(void* const* d_in, const int* in_sizes, int n_in,
                              void* d_out, int out_size) {
    const float* x     = (const float*)d_in[0];
    const int*   ei    = (const int*)  d_in[1];
    const float* ef    = (const float*)d_in[2];
    const float* ew    = (const float*)d_in[3];
    const float* Wq    = (const float*)d_in[4];
    const float* bq    = (const float*)d_in[5];
    const float* Wk    = (const float*)d_in[6];
    const float* bk    = (const float*)d_in[7];
    const float* Wv    = (const float*)d_in[8];
    const float* bv    = (const float*)d_in[9];
    const float* We    = (const float*)d_in[10];
    const float* be    = (const float*)d_in[11];
    const float* Wo    = (const float*)d_in[12];
    const float* bo    = (const float*)d_in[13];
    const float* W1    = (const float*)d_in[14];
    const float* b1    = (const float*)d_in[15];
    const float* W2    = (const float*)d_in[16];
    const float* b2    = (const float*)d_in[17];
    const float* g1    = (const float*)d_in[18];
    const float* be1   = (const float*)d_in[19];
    const float* g2    = (const float*)d_in[20];
    const float* be2   = (const float*)d_in[21];
    const float* alpha = (const float*)d_in[22];
    const float* beta  = (const float*)d_in[23];

    float* out = (float*)d_out;
    float* out_x = out;
    float* out_attn = nullptr;
    if (out_size >= NN*DD + NE*HH) out_attn = out + (size_t)NN*DD;

    float *p_qkv, *p_agg, *p_x1, *p_bqkv;
    __nv_bfloat16 *p_xnh, *p_xnl, *p_aggh, *p_aggl, *p_hh, *p_hl, *p_wh, *p_wl;
    cudaGetSymbolAddress((void**)&p_qkv,  g_qkv);
    cudaGetSymbolAddress((void**)&p_agg,  g_agg);
    cudaGetSymbolAddress((void**)&p_x1,   g_x1);
    cudaGetSymbolAddress((void**)&p_bqkv, g_bqkv);
    cudaGetSymbolAddress((void**)&p_xnh,  g_xnh);
    cudaGetSymbolAddress((void**)&p_xnl,  g_xnl);
    cudaGetSymbolAddress((void**)&p_aggh, g_aggh);
    cudaGetSymbolAddress((void**)&p_aggl, g_aggl);
    cudaGetSymbolAddress((void**)&p_hh,   g_hh);
    cudaGetSymbolAddress((void**)&p_hl,   g_hl);
    cudaGetSymbolAddress((void**)&p_wh,   g_wh);
    cudaGetSymbolAddress((void**)&p_wl,   g_wl);

    cudaFuncSetAttribute(tc_gemm<0>, cudaFuncAttributeMaxDynamicSharedMemorySize, GEMM_SMEM);
    cudaFuncSetAttribute(tc_gemm<1>, cudaFuncAttributeMaxDynamicSharedMemorySize, GEMM_SMEM);
    cudaFuncSetAttribute(tc_gemm<2>, cudaFuncAttributeMaxDynamicSharedMemorySize, GEMM_SMEM);

    const int eblocks = (NE + 7) / 8;
    const int mtiles = (NN + 127) / 128;   // 391

    // 1. zero accumulators
    zero_kernel<<<(NN*DD + 255) / 256, 256>>>();

    // 2. all weight/bias conversions in one launch
    cvt_all<<<(WTOT/4 + 255) / 256, 256>>>(Wq, Wk, Wv, Wo, W1, W2, bq, bk, bv);

    // 3. LN1 -> bf16 hi/lo
    ln_kernel<<<NN, 256>>>(x, g1, be1, p_xnh, p_xnl);

    // 4. edge projection (thread-per-edge)
    ep_kernel<<<(NE + 255) / 256, 256>>>(ef, We, be);

    // 5. fused qkv projection (launch #5 -> ncu profile target)
    dim3 gqkv(DQKV/128, mtiles);
    tc_gemm<0><<<gqkv, 256, GEMM_SMEM>>>(p_xnh, p_xnl, p_wh + WQO, p_wl + WQO,
                                         p_bqkv, p_qkv, nullptr, nullptr,
                                         NN, DQKV, DD, nullptr, nullptr);

    // 6. scores + segment max
    scores_kernel<<<eblocks, 256>>>(ei, ew);

    // 7. fused exp + ssum + unnormalized scatter-aggregate
    expagg_kernel<<<eblocks, 256>>>(ei);

    // 8. attn weights output
    if (out_attn)
        attnw_kernel<<<(NE + 255) / 256, 256>>>(ei, out_attn);

    // 9. normalize agg + convert to bf16 hi/lo
    cvt_agg_norm<<<(NN*DD/4 + 255) / 256, 256>>>(NN*DD/4);

    // 10. attn out projection + residual
    dim3 g256(DD/128, mtiles);
    tc_gemm<1><<<g256, 256, GEMM_SMEM>>>(p_aggh, p_aggl, p_wh + WOO, p_wl + WOO,
                                         bo, p_x1, nullptr, nullptr, NN, DD, DD, x, alpha);

    // 11. LN2 -> bf16 hi/lo
    ln_kernel<<<NN, 256>>>(p_x1, g2, be2, p_xnh, p_xnl);

    // 12. FFN up + GELU -> bf16 hi/lo h
    dim3 g1024(D4/128, mtiles);
    tc_gemm<2><<<g1024, 256, GEMM_SMEM>>>(p_xnh, p_xnl, p_wh + W1O, p_wl + W1O,
                                          b1, nullptr, p_hh, p_hl, NN, D4, DD, nullptr, nullptr);

    // 13. FFN down + residual -> final x into d_out
    tc_gemm<1><<<g256, 256, GEMM_SMEM>>>(p_hh, p_hl, p_wh + W2O, p_wl + W2O,
                                         b2, out_x, nullptr, nullptr, NN, DD, D4, p_x1, beta);
}